// round 11
// baseline (speedup 1.0000x reference)
#include <cuda_runtime.h>
#include <cuda_fp16.h>
#include <cstdint>
#include <cstddef>

// ---------------------------------------------------------------------------
// Fixed shapes: N=100000, E=1600000, F 128 -> 128 -> 64
// ---------------------------------------------------------------------------
#define MAX_N 100000
#define MAX_E 1600000
#define SCAN_CHUNK 1024
#define MAX_CHUNKS ((MAX_N + SCAN_CHUNK - 1) / SCAN_CHUNK)   // 98

// Scratch (device BSS — no allocation inside kernel_launch)
__device__ __half g_half[(size_t)MAX_N * 128];   // x @ W1, fp16 (gather-optimized)
__device__ __half p_half[(size_t)MAX_N * 64];    // spmm1+gemm2 fused output, fp16

__device__ int   deg_buf   [MAX_N];
__device__ int   row_ptr   [MAX_N + 1];
__device__ int   cursor    [MAX_N];
__device__ int   part_buf  [MAX_CHUNKS];
__device__ int   partoff   [MAX_CHUNKS];
__device__ int2  edge_sorted[MAX_E];             // packed (src, w_bits)

// ---------------------------------------------------------------------------
// Threefry-2x32, key = (0, 42) — bit-exact replica of jax threefry2x32 core
// ---------------------------------------------------------------------------
__device__ __forceinline__ void threefry_0_42(uint32_t x0, uint32_t x1,
                                              uint32_t& o0, uint32_t& o1)
{
    const uint32_t k0 = 0u, k1 = 42u;
    const uint32_t k2 = k0 ^ k1 ^ 0x1BD11BDAu;
    x0 += k0; x1 += k1;
#define TF_R(r) { x0 += x1; x1 = (x1 << (r)) | (x1 >> (32 - (r))); x1 ^= x0; }
    TF_R(13) TF_R(15) TF_R(26) TF_R(6)   x0 += k1; x1 += k2 + 1u;
    TF_R(17) TF_R(29) TF_R(16) TF_R(24)  x0 += k2; x1 += k0 + 2u;
    TF_R(13) TF_R(15) TF_R(26) TF_R(6)   x0 += k0; x1 += k1 + 3u;
    TF_R(17) TF_R(29) TF_R(16) TF_R(24)  x0 += k1; x1 += k2 + 4u;
    TF_R(13) TF_R(15) TF_R(26) TF_R(6)   x0 += k2; x1 += k0 + 5u;
#undef TF_R
    o0 = x0; o1 = x1;
}

__device__ __forceinline__ bool drop_mask(uint32_t i)
{
    uint32_t o0, o1;
    threefry_0_42(0u, i, o0, o1);
    return ((o0 ^ o1) & 0x80000000u) != 0u;   // true = drop (XOR-fold)
}

// ---------------------------------------------------------------------------
// Packed fp32x2 FMA helpers (FFMA2)
// ---------------------------------------------------------------------------
#define FMA2(acc_, a_, b_) \
    asm("fma.rn.f32x2 %0, %1, %2, %0;" : "+l"(acc_) : "l"(a_), "l"(b_))

__device__ __forceinline__ unsigned long long dup2(float a)
{
    unsigned long long r;
    asm("mov.b64 %0, {%1, %1};" : "=l"(r) : "r"(__float_as_uint(a)));
    return r;
}

__device__ __forceinline__ uint32_t pack_half2_from(unsigned long long v64)
{
    const float lo = __uint_as_float((unsigned)(v64 & 0xffffffffu));
    const float hi = __uint_as_float((unsigned)(v64 >> 32));
    const __half2 h = __floats2half2_rn(lo, hi);
    return *reinterpret_cast<const uint32_t*>(&h);
}

// ===========================================================================
// GEMM1 (FFMA2):  g_half[M,128] = x[M,128] @ W1[128,128], fp16 output
// ===========================================================================
__global__ void __launch_bounds__(256, 2)
gemm1_k128(const float* __restrict__ A, const float* __restrict__ B, int M)
{
    constexpr int BN = 128;
    __shared__ __align__(16) float As[2][16 * 128];
    __shared__ __align__(16) float Bs[2][16 * BN];

    const int tid = threadIdx.x;
    const int tx  = tid & 15;
    const int ty  = tid >> 4;
    const int m0  = blockIdx.x * 128;
    const int lr  = tid >> 2;
    const int lc  = tid & 3;

    unsigned long long acc[8][4];
#pragma unroll
    for (int r = 0; r < 8; r++)
#pragma unroll
        for (int j = 0; j < 4; j++) acc[r][j] = 0ull;

    auto loadTiles = [&](int buf, int kk) {
#pragma unroll
        for (int rr = 0; rr < 2; rr++) {
            int row = m0 + lr + rr * 64;
            if (row > M - 1) row = M - 1;
            const float4 v = *(const float4*)(A + (size_t)row * 128 + kk + lc * 4);
            float* d = &As[buf][0];
            const int mi = lr + rr * 64;
            d[(lc * 4 + 0) * 128 + mi] = v.x;
            d[(lc * 4 + 1) * 128 + mi] = v.y;
            d[(lc * 4 + 2) * 128 + mi] = v.z;
            d[(lc * 4 + 3) * 128 + mi] = v.w;
        }
#pragma unroll
        for (int i = 0; i < 2; i++) {
            const int idx = (i * 256 + tid) * 4;
            *(float4*)&Bs[buf][idx] = *(const float4*)(B + kk * BN + idx);
        }
    };

    loadTiles(0, 0);
    __syncthreads();

#pragma unroll 1
    for (int kk = 0; kk < 128; kk += 16) {
        const int cur = (kk >> 4) & 1;
        if (kk + 16 < 128) loadTiles(cur ^ 1, kk + 16);
#pragma unroll
        for (int k = 0; k < 16; k++) {
            const float4 a0 = *(const float4*)&As[cur][k * 128 + ty * 4];
            const float4 a1 = *(const float4*)&As[cur][k * 128 + ty * 4 + 64];
            unsigned long long a2[8];
            a2[0] = dup2(a0.x); a2[1] = dup2(a0.y);
            a2[2] = dup2(a0.z); a2[3] = dup2(a0.w);
            a2[4] = dup2(a1.x); a2[5] = dup2(a1.y);
            a2[6] = dup2(a1.z); a2[7] = dup2(a1.w);
#pragma unroll
            for (int g = 0; g < 2; g++) {
                const double2 b = *(const double2*)&Bs[cur][k * BN + tx * 4 + g * 64];
                const unsigned long long bl = __double_as_longlong(b.x);
                const unsigned long long bh = __double_as_longlong(b.y);
#pragma unroll
                for (int r = 0; r < 8; r++) {
                    FMA2(acc[r][2 * g + 0], a2[r], bl);
                    FMA2(acc[r][2 * g + 1], a2[r], bh);
                }
            }
        }
        __syncthreads();
    }

#pragma unroll
    for (int r = 0; r < 8; r++) {
        const int row = m0 + ty * 4 + (r >> 2) * 64 + (r & 3);
        if (row < M) {
#pragma unroll
            for (int g = 0; g < 2; g++) {
                uint2 o;
                o.x = pack_half2_from(acc[r][2 * g + 0]);
                o.y = pack_half2_from(acc[r][2 * g + 1]);
                *(uint2*)(g_half + (size_t)row * 128 + tx * 4 + g * 64) = o;
            }
        }
    }
}

// ===========================================================================
// CSR build: deg -> scan -> scatter (packed payload)
// ===========================================================================
__global__ void k_zero_deg(int N)
{
    const int i = blockIdx.x * blockDim.x + threadIdx.x;
    if (i < N) deg_buf[i] = 0;
}

__global__ void k_hist(const int* __restrict__ dst, int E)
{
    const int e = blockIdx.x * blockDim.x + threadIdx.x;
    if (e < E) atomicAdd(&deg_buf[dst[e]], 1);
}

__global__ void k_part_sums(int N)
{
    __shared__ int sm[256];
    const int b = blockIdx.x, t = threadIdx.x;
    int s = 0;
#pragma unroll
    for (int k = 0; k < 4; k++) {
        const int i = b * SCAN_CHUNK + k * 256 + t;
        if (i < N) s += deg_buf[i];
    }
    sm[t] = s; __syncthreads();
    for (int off = 128; off > 0; off >>= 1) {
        if (t < off) sm[t] += sm[t + off];
        __syncthreads();
    }
    if (t == 0) part_buf[b] = sm[0];
}

__global__ void k_scan_parts(int nchunks, int N, int E)
{
    __shared__ int sm[128];
    const int t = threadIdx.x;
    const int v = (t < nchunks) ? part_buf[t] : 0;
    sm[t] = v; __syncthreads();
#pragma unroll
    for (int off = 1; off < 128; off <<= 1) {
        const int x = (t >= off) ? sm[t - off] : 0;
        __syncthreads();
        sm[t] += x;
        __syncthreads();
    }
    if (t < nchunks) partoff[t] = sm[t] - v;
    if (t == 0) row_ptr[N] = E;
}

__global__ void k_scan_chunks(int N)
{
    __shared__ int sm[SCAN_CHUNK];
    const int b = blockIdx.x, t = threadIdx.x;
    const int i = b * SCAN_CHUNK + t;
    const int v = (i < N) ? deg_buf[i] : 0;
    sm[t] = v; __syncthreads();
#pragma unroll
    for (int off = 1; off < SCAN_CHUNK; off <<= 1) {
        const int x = (t >= off) ? sm[t - off] : 0;
        __syncthreads();
        sm[t] += x;
        __syncthreads();
    }
    if (i < N) {
        const int ex = sm[t] - v + partoff[b];
        row_ptr[i] = ex;
        cursor[i]  = ex;
    }
}

__global__ void k_scatter(const int* __restrict__ src, const int* __restrict__ dst,
                          const float* __restrict__ ew, int E)
{
    const int e = blockIdx.x * blockDim.x + threadIdx.x;
    if (e >= E) return;
    const int pos = atomicAdd(&cursor[dst[e]], 1);
    int2 pkt;
    pkt.x = src[e];
    pkt.y = __float_as_int(ew[e]);
    edge_sorted[pos] = pkt;
}

// ===========================================================================
// FUSED SpMM1 + bias/relu/dropout + GEMM2:
//   per dst d:  h_row = relu(spmm(A,g)[d] + b1) * mask * 2   (kept in smem)
//               p[d]  = h_row @ W2                           (fp16 output)
// One warp per dst (8 warps/CTA). W2 (fp32, 32 KB) shared per CTA.
// h never touches global memory; gemm2 kernel eliminated.
// ===========================================================================
__global__ void __launch_bounds__(256)
spmm1_gemm2_fused(const float* __restrict__ b1, const float* __restrict__ W2, int N)
{
    __shared__ __align__(16) float W2s[128 * 64];    // 32 KB
    __shared__ float hs[8][128];                     // 4 KB (per-warp h row)

    const int tid  = threadIdx.x;
    const int wid  = tid >> 5;
    const int lane = tid & 31;

    // Load W2 once per CTA (coalesced float4)
#pragma unroll
    for (int i = 0; i < 8; i++)
        ((float4*)W2s)[i * 256 + tid] = ((const float4*)W2)[i * 256 + tid];
    __syncthreads();

    const int d = blockIdx.x * 8 + wid;
    if (d >= N) return;

    const int beg = row_ptr[d];
    const int end = row_ptr[d + 1];

    // --- gather phase: acc = spmm(A, g)[d], lane owns 4 features ---
    float4 acc = make_float4(0.f, 0.f, 0.f, 0.f);
    const __half* __restrict__ G = g_half;

    int j = beg;
    for (; j + 8 <= end; j += 8) {
        int2 e[8];
#pragma unroll
        for (int q = 0; q < 8; q++) e[q] = __ldg(&edge_sorted[j + q]);
        uint2 gv[8];
#pragma unroll
        for (int q = 0; q < 8; q++)
            gv[q] = *(const uint2*)(G + (size_t)e[q].x * 128 + lane * 4);
#pragma unroll
        for (int q = 0; q < 8; q++) {
            const float w = __int_as_float(e[q].y);
            const float2 f0 = __half22float2(*reinterpret_cast<const __half2*>(&gv[q].x));
            const float2 f1 = __half22float2(*reinterpret_cast<const __half2*>(&gv[q].y));
            acc.x += w * f0.x; acc.y += w * f0.y;
            acc.z += w * f1.x; acc.w += w * f1.y;
        }
    }
    for (; j < end; j++) {
        const int2 e = __ldg(&edge_sorted[j]);
        const float w = __int_as_float(e.y);
        const uint2 gv = *(const uint2*)(G + (size_t)e.x * 128 + lane * 4);
        const float2 f0 = __half22float2(*reinterpret_cast<const __half2*>(&gv.x));
        const float2 f1 = __half22float2(*reinterpret_cast<const __half2*>(&gv.y));
        acc.x += w * f0.x; acc.y += w * f0.y;
        acc.z += w * f1.x; acc.w += w * f1.y;
    }

    // --- epilogue: h = relu(acc + b1) * mask * 2, parked in smem ---
    const float4 bv = *(const float4*)(b1 + lane * 4);
    const uint32_t base = (uint32_t)d * 128u + (uint32_t)lane * 4u;

    float v0 = fmaxf(acc.x + bv.x, 0.f);
    float v1 = fmaxf(acc.y + bv.y, 0.f);
    float v2 = fmaxf(acc.z + bv.z, 0.f);
    float v3 = fmaxf(acc.w + bv.w, 0.f);
    float* hrow = hs[wid];
    hrow[lane * 4 + 0] = drop_mask(base + 0u) ? 0.f : v0 * 2.f;
    hrow[lane * 4 + 1] = drop_mask(base + 1u) ? 0.f : v1 * 2.f;
    hrow[lane * 4 + 2] = drop_mask(base + 2u) ? 0.f : v2 * 2.f;
    hrow[lane * 4 + 3] = drop_mask(base + 3u) ? 0.f : v3 * 2.f;
    __syncwarp();

    // --- gemm2 phase: p[d] = h_row @ W2, lane owns 2 output features ---
    const int n0 = lane * 2;
    float a0 = 0.f, a1 = 0.f;
#pragma unroll 8
    for (int k = 0; k < 128; k++) {
        const float hk = hrow[k];                       // smem broadcast
        const float2 w = *(const float2*)&W2s[k * 64 + n0];
        a0 = fmaf(hk, w.x, a0);
        a1 = fmaf(hk, w.y, a1);
    }
    const __half2 ph = __floats2half2_rn(a0, a1);
    *(__half2*)(p_half + (size_t)d * 64 + n0) = ph;
}

// ===========================================================================
// SpMM2 (CSR, F=64, fp16 gather) fused with +b2. Lane owns 2 features.
// ===========================================================================
__global__ void __launch_bounds__(256)
spmm2_fused(const float* __restrict__ b2, float* __restrict__ out, int N)
{
    const int d    = (blockIdx.x * blockDim.x + threadIdx.x) >> 5;
    const int lane = threadIdx.x & 31;
    if (d >= N) return;

    const int beg = row_ptr[d];
    const int end = row_ptr[d + 1];

    float2 acc = make_float2(0.f, 0.f);
    const __half* __restrict__ P = p_half;

    int j = beg;
    for (; j + 8 <= end; j += 8) {
        int2 e[8];
#pragma unroll
        for (int q = 0; q < 8; q++) e[q] = __ldg(&edge_sorted[j + q]);
        __half2 pv[8];
#pragma unroll
        for (int q = 0; q < 8; q++)
            pv[q] = *(const __half2*)(P + (size_t)e[q].x * 64 + lane * 2);
#pragma unroll
        for (int q = 0; q < 8; q++) {
            const float w = __int_as_float(e[q].y);
            const float2 f = __half22float2(pv[q]);
            acc.x += w * f.x; acc.y += w * f.y;
        }
    }
    for (; j < end; j++) {
        const int2 e = __ldg(&edge_sorted[j]);
        const float w = __int_as_float(e.y);
        const float2 f = __half22float2(*(const __half2*)(P + (size_t)e.x * 64 + lane * 2));
        acc.x += w * f.x; acc.y += w * f.y;
    }

    const float2 bv = *(const float2*)(b2 + lane * 2);
    float2 o; o.x = acc.x + bv.x; o.y = acc.y + bv.y;
    *(float2*)(out + (size_t)d * 64 + lane * 2) = o;
}

// ---------------------------------------------------------------------------
// kernel_launch
// inputs: x, edge_weight, W1, b1, W2, b2, src, dst, n_nodes
// ---------------------------------------------------------------------------
extern "C" void kernel_launch(void* const* d_in, const int* in_sizes, int n_in,
                              void* d_out, int out_size)
{
    const float* x   = (const float*)d_in[0];
    const float* ew  = (const float*)d_in[1];
    const float* W1  = (const float*)d_in[2];
    const float* b1  = (const float*)d_in[3];
    const float* W2  = (const float*)d_in[4];
    const float* b2  = (const float*)d_in[5];
    const int*   src = (const int*)d_in[6];
    const int*   dst = (const int*)d_in[7];

    const int N = in_sizes[0] / 128;
    const int E = in_sizes[1];
    float* out = (float*)d_out;

    const int nchunks = (N + SCAN_CHUNK - 1) / SCAN_CHUNK;

    static cudaStream_t s2 = nullptr;
    static cudaEvent_t  ev_fork = nullptr, ev_join = nullptr;
    static bool tried = false;
    if (!tried) {
        tried = true;
        if (cudaStreamCreateWithFlags(&s2, cudaStreamNonBlocking) != cudaSuccess) s2 = nullptr;
        if (s2) {
            cudaEventCreateWithFlags(&ev_fork, cudaEventDisableTiming);
            cudaEventCreateWithFlags(&ev_join, cudaEventDisableTiming);
        }
    }

    cudaStream_t cs = s2 ? s2 : (cudaStream_t)0;

    if (s2) {
        cudaEventRecord(ev_fork, 0);
        cudaStreamWaitEvent(s2, ev_fork, 0);
    }

    // --- CSR build on secondary stream (independent of gemm1) ---
    k_zero_deg   <<<(N + 255) / 256, 256, 0, cs>>>(N);
    k_hist       <<<(E + 255) / 256, 256, 0, cs>>>(dst, E);
    k_part_sums  <<<nchunks, 256, 0, cs>>>(N);
    k_scan_parts <<<1, 128, 0, cs>>>(nchunks, N, E);
    k_scan_chunks<<<nchunks, SCAN_CHUNK, 0, cs>>>(N);
    k_scatter    <<<(E + 255) / 256, 256, 0, cs>>>(src, dst, ew, E);

    if (s2) cudaEventRecord(ev_join, s2);

    // --- gemm1 on main stream, overlapped with CSR build ---
    gemm1_k128<<<(N + 127) / 128, 256>>>(x, W1, N);

    if (s2) cudaStreamWaitEvent((cudaStream_t)0, ev_join, 0);

    // p = (relu(spmm(A, g) + b1) * mask * 2) @ W2   — fused, h never global
    spmm1_gemm2_fused<<<(N + 7) / 8, 256>>>(b1, W2, N);
    // out = spmm(A, p) + b2
    spmm2_fused<<<(N * 32 + 255) / 256, 256>>>(b2, out, N);
}

// round 12
// speedup vs baseline: 1.1231x; 1.1231x over previous
#include <cuda_runtime.h>
#include <cuda_fp16.h>
#include <cstdint>
#include <cstddef>

// ---------------------------------------------------------------------------
// Fixed shapes: N=100000, E=1600000, F 128 -> 128 -> 64
// ---------------------------------------------------------------------------
#define MAX_N 100000
#define MAX_E 1600000
#define SCAN_CHUNK 1024
#define MAX_CHUNKS ((MAX_N + SCAN_CHUNK - 1) / SCAN_CHUNK)   // 98

// Scratch (device BSS — no allocation inside kernel_launch)
__device__ __half   g_half[(size_t)MAX_N * 128];  // x @ W1, fp16
__device__ __half   h_half[(size_t)MAX_N * 128];  // relu+bias+dropout, fp16
__device__ __half   p_half[(size_t)MAX_N * 64];   // h @ W2, fp16
__device__ uint32_t mask_buf[(size_t)MAX_N * 4];  // packed drop bits (128/node)

__device__ int   deg_buf   [MAX_N];
__device__ int   row_ptr   [MAX_N + 1];
__device__ int   cursor    [MAX_N];
__device__ int   part_buf  [MAX_CHUNKS];
__device__ int   partoff   [MAX_CHUNKS];
__device__ int2  edge_sorted[MAX_E];              // packed (src, w_bits)

// ---------------------------------------------------------------------------
// Threefry-2x32, key = (0, 42) — bit-exact replica of jax threefry2x32 core
// ---------------------------------------------------------------------------
__device__ __forceinline__ void threefry_0_42(uint32_t x0, uint32_t x1,
                                              uint32_t& o0, uint32_t& o1)
{
    const uint32_t k0 = 0u, k1 = 42u;
    const uint32_t k2 = k0 ^ k1 ^ 0x1BD11BDAu;
    x0 += k0; x1 += k1;
#define TF_R(r) { x0 += x1; x1 = (x1 << (r)) | (x1 >> (32 - (r))); x1 ^= x0; }
    TF_R(13) TF_R(15) TF_R(26) TF_R(6)   x0 += k1; x1 += k2 + 1u;
    TF_R(17) TF_R(29) TF_R(16) TF_R(24)  x0 += k2; x1 += k0 + 2u;
    TF_R(13) TF_R(15) TF_R(26) TF_R(6)   x0 += k0; x1 += k1 + 3u;
    TF_R(17) TF_R(29) TF_R(16) TF_R(24)  x0 += k1; x1 += k2 + 4u;
    TF_R(13) TF_R(15) TF_R(26) TF_R(6)   x0 += k2; x1 += k0 + 5u;
#undef TF_R
    o0 = x0; o1 = x1;
}

// ===========================================================================
// Mask precompute: bit i of mask_buf[i>>5] = drop(element i)  (XOR-fold)
// Pure ALU, zero data dependencies — runs overlapped in the fork phase.
// ===========================================================================
__global__ void k_mask(int TOT)
{
    const int i = blockIdx.x * blockDim.x + threadIdx.x;
    bool drop = false;
    if (i < TOT) {
        uint32_t o0, o1;
        threefry_0_42(0u, (uint32_t)i, o0, o1);
        drop = ((o0 ^ o1) & 0x80000000u) != 0u;
    }
    const uint32_t b = __ballot_sync(0xffffffffu, drop);
    if ((threadIdx.x & 31) == 0 && i < TOT) mask_buf[i >> 5] = b;
}

// ---------------------------------------------------------------------------
// Packed fp32x2 FMA helpers (FFMA2)
// ---------------------------------------------------------------------------
#define FMA2(acc_, a_, b_) \
    asm("fma.rn.f32x2 %0, %1, %2, %0;" : "+l"(acc_) : "l"(a_), "l"(b_))

__device__ __forceinline__ unsigned long long dup2(float a)
{
    unsigned long long r;
    asm("mov.b64 %0, {%1, %1};" : "=l"(r) : "r"(__float_as_uint(a)));
    return r;
}

__device__ __forceinline__ uint32_t pack_half2_from(unsigned long long v64)
{
    const float lo = __uint_as_float((unsigned)(v64 & 0xffffffffu));
    const float hi = __uint_as_float((unsigned)(v64 >> 32));
    const __half2 h = __floats2half2_rn(lo, hi);
    return *reinterpret_cast<const uint32_t*>(&h);
}

// ===========================================================================
// GEMM1 (FFMA2):  g_half[M,128] = x[M,128] @ W1[128,128], fp16 output
// ===========================================================================
__global__ void __launch_bounds__(256, 2)
gemm1_k128(const float* __restrict__ A, const float* __restrict__ B, int M)
{
    constexpr int BN = 128;
    __shared__ __align__(16) float As[2][16 * 128];
    __shared__ __align__(16) float Bs[2][16 * BN];

    const int tid = threadIdx.x;
    const int tx  = tid & 15;
    const int ty  = tid >> 4;
    const int m0  = blockIdx.x * 128;
    const int lr  = tid >> 2;
    const int lc  = tid & 3;

    unsigned long long acc[8][4];
#pragma unroll
    for (int r = 0; r < 8; r++)
#pragma unroll
        for (int j = 0; j < 4; j++) acc[r][j] = 0ull;

    auto loadTiles = [&](int buf, int kk) {
#pragma unroll
        for (int rr = 0; rr < 2; rr++) {
            int row = m0 + lr + rr * 64;
            if (row > M - 1) row = M - 1;
            const float4 v = *(const float4*)(A + (size_t)row * 128 + kk + lc * 4);
            float* d = &As[buf][0];
            const int mi = lr + rr * 64;
            d[(lc * 4 + 0) * 128 + mi] = v.x;
            d[(lc * 4 + 1) * 128 + mi] = v.y;
            d[(lc * 4 + 2) * 128 + mi] = v.z;
            d[(lc * 4 + 3) * 128 + mi] = v.w;
        }
#pragma unroll
        for (int i = 0; i < 2; i++) {
            const int idx = (i * 256 + tid) * 4;
            *(float4*)&Bs[buf][idx] = *(const float4*)(B + kk * BN + idx);
        }
    };

    loadTiles(0, 0);
    __syncthreads();

#pragma unroll 1
    for (int kk = 0; kk < 128; kk += 16) {
        const int cur = (kk >> 4) & 1;
        if (kk + 16 < 128) loadTiles(cur ^ 1, kk + 16);
#pragma unroll
        for (int k = 0; k < 16; k++) {
            const float4 a0 = *(const float4*)&As[cur][k * 128 + ty * 4];
            const float4 a1 = *(const float4*)&As[cur][k * 128 + ty * 4 + 64];
            unsigned long long a2[8];
            a2[0] = dup2(a0.x); a2[1] = dup2(a0.y);
            a2[2] = dup2(a0.z); a2[3] = dup2(a0.w);
            a2[4] = dup2(a1.x); a2[5] = dup2(a1.y);
            a2[6] = dup2(a1.z); a2[7] = dup2(a1.w);
#pragma unroll
            for (int g = 0; g < 2; g++) {
                const double2 b = *(const double2*)&Bs[cur][k * BN + tx * 4 + g * 64];
                const unsigned long long bl = __double_as_longlong(b.x);
                const unsigned long long bh = __double_as_longlong(b.y);
#pragma unroll
                for (int r = 0; r < 8; r++) {
                    FMA2(acc[r][2 * g + 0], a2[r], bl);
                    FMA2(acc[r][2 * g + 1], a2[r], bh);
                }
            }
        }
        __syncthreads();
    }

#pragma unroll
    for (int r = 0; r < 8; r++) {
        const int row = m0 + ty * 4 + (r >> 2) * 64 + (r & 3);
        if (row < M) {
#pragma unroll
            for (int g = 0; g < 2; g++) {
                uint2 o;
                o.x = pack_half2_from(acc[r][2 * g + 0]);
                o.y = pack_half2_from(acc[r][2 * g + 1]);
                *(uint2*)(g_half + (size_t)row * 128 + tx * 4 + g * 64) = o;
            }
        }
    }
}

// ===========================================================================
// GEMM2 (FFMA2):  p_half[M,64] = h_half[M,128] @ W2[128,64]
// A is fp16 (converted to fp32 in the SMEM staging), math fp32.
// ===========================================================================
__global__ void __launch_bounds__(256, 2)
gemm2_k128(const float* __restrict__ B, int M)
{
    constexpr int BN = 64;
    const __half* __restrict__ A = h_half;

    __shared__ __align__(16) float As[2][16 * 128];
    __shared__ __align__(16) float Bs[2][16 * BN];

    const int tid = threadIdx.x;
    const int tx  = tid & 15;
    const int ty  = tid >> 4;
    const int m0  = blockIdx.x * 128;
    const int lr  = tid >> 2;
    const int lc  = tid & 3;

    unsigned long long acc[8][2];
#pragma unroll
    for (int r = 0; r < 8; r++) { acc[r][0] = 0ull; acc[r][1] = 0ull; }

    auto loadTiles = [&](int buf, int kk) {
#pragma unroll
        for (int rr = 0; rr < 2; rr++) {
            int row = m0 + lr + rr * 64;
            if (row > M - 1) row = M - 1;
            const uint2 hv = *(const uint2*)(A + (size_t)row * 128 + kk + lc * 4);
            const float2 f0 = __half22float2(*reinterpret_cast<const __half2*>(&hv.x));
            const float2 f1 = __half22float2(*reinterpret_cast<const __half2*>(&hv.y));
            float* d = &As[buf][0];
            const int mi = lr + rr * 64;
            d[(lc * 4 + 0) * 128 + mi] = f0.x;
            d[(lc * 4 + 1) * 128 + mi] = f0.y;
            d[(lc * 4 + 2) * 128 + mi] = f1.x;
            d[(lc * 4 + 3) * 128 + mi] = f1.y;
        }
        {
            const int idx = tid * 4;
            if (idx < 16 * BN)
                *(float4*)&Bs[buf][idx] = *(const float4*)(B + kk * BN + idx);
        }
    };

    loadTiles(0, 0);
    __syncthreads();

#pragma unroll 1
    for (int kk = 0; kk < 128; kk += 16) {
        const int cur = (kk >> 4) & 1;
        if (kk + 16 < 128) loadTiles(cur ^ 1, kk + 16);
#pragma unroll
        for (int k = 0; k < 16; k++) {
            const float4 a0 = *(const float4*)&As[cur][k * 128 + ty * 4];
            const float4 a1 = *(const float4*)&As[cur][k * 128 + ty * 4 + 64];
            unsigned long long a2[8];
            a2[0] = dup2(a0.x); a2[1] = dup2(a0.y);
            a2[2] = dup2(a0.z); a2[3] = dup2(a0.w);
            a2[4] = dup2(a1.x); a2[5] = dup2(a1.y);
            a2[6] = dup2(a1.z); a2[7] = dup2(a1.w);
            const double2 b = *(const double2*)&Bs[cur][k * BN + tx * 4];
            const unsigned long long bl = __double_as_longlong(b.x);
            const unsigned long long bh = __double_as_longlong(b.y);
#pragma unroll
            for (int r = 0; r < 8; r++) {
                FMA2(acc[r][0], a2[r], bl);
                FMA2(acc[r][1], a2[r], bh);
            }
        }
        __syncthreads();
    }

#pragma unroll
    for (int r = 0; r < 8; r++) {
        const int row = m0 + ty * 4 + (r >> 2) * 64 + (r & 3);
        if (row < M) {
            uint2 o;
            o.x = pack_half2_from(acc[r][0]);
            o.y = pack_half2_from(acc[r][1]);
            *(uint2*)(p_half + (size_t)row * 64 + tx * 4) = o;
        }
    }
}

// ===========================================================================
// CSR build: deg -> scan -> scatter (packed payload)
// ===========================================================================
__global__ void k_zero_deg(int N)
{
    const int i = blockIdx.x * blockDim.x + threadIdx.x;
    if (i < N) deg_buf[i] = 0;
}

__global__ void k_hist(const int* __restrict__ dst, int E)
{
    const int e = blockIdx.x * blockDim.x + threadIdx.x;
    if (e < E) atomicAdd(&deg_buf[dst[e]], 1);
}

__global__ void k_part_sums(int N)
{
    __shared__ int sm[256];
    const int b = blockIdx.x, t = threadIdx.x;
    int s = 0;
#pragma unroll
    for (int k = 0; k < 4; k++) {
        const int i = b * SCAN_CHUNK + k * 256 + t;
        if (i < N) s += deg_buf[i];
    }
    sm[t] = s; __syncthreads();
    for (int off = 128; off > 0; off >>= 1) {
        if (t < off) sm[t] += sm[t + off];
        __syncthreads();
    }
    if (t == 0) part_buf[b] = sm[0];
}

__global__ void k_scan_parts(int nchunks, int N, int E)
{
    __shared__ int sm[128];
    const int t = threadIdx.x;
    const int v = (t < nchunks) ? part_buf[t] : 0;
    sm[t] = v; __syncthreads();
#pragma unroll
    for (int off = 1; off < 128; off <<= 1) {
        const int x = (t >= off) ? sm[t - off] : 0;
        __syncthreads();
        sm[t] += x;
        __syncthreads();
    }
    if (t < nchunks) partoff[t] = sm[t] - v;
    if (t == 0) row_ptr[N] = E;
}

__global__ void k_scan_chunks(int N)
{
    __shared__ int sm[SCAN_CHUNK];
    const int b = blockIdx.x, t = threadIdx.x;
    const int i = b * SCAN_CHUNK + t;
    const int v = (i < N) ? deg_buf[i] : 0;
    sm[t] = v; __syncthreads();
#pragma unroll
    for (int off = 1; off < SCAN_CHUNK; off <<= 1) {
        const int x = (t >= off) ? sm[t - off] : 0;
        __syncthreads();
        sm[t] += x;
        __syncthreads();
    }
    if (i < N) {
        const int ex = sm[t] - v + partoff[b];
        row_ptr[i] = ex;
        cursor[i]  = ex;
    }
}

__global__ void k_scatter(const int* __restrict__ src, const int* __restrict__ dst,
                          const float* __restrict__ ew, int E)
{
    const int e = blockIdx.x * blockDim.x + threadIdx.x;
    if (e >= E) return;
    const int pos = atomicAdd(&cursor[dst[e]], 1);
    int2 pkt;
    pkt.x = src[e];
    pkt.y = __float_as_int(ew[e]);
    edge_sorted[pos] = pkt;
}

// ===========================================================================
// SpMM1 (CSR, F=128, fp16 gather) + bias/relu/dropout epilogue.
// Dropout bits precomputed (mask_buf); fp16 h output.
// ===========================================================================
__global__ void __launch_bounds__(256)
spmm1_fused(const float* __restrict__ b1, int N)
{
    const int d    = (blockIdx.x * blockDim.x + threadIdx.x) >> 5;
    const int lane = threadIdx.x & 31;
    if (d >= N) return;

    const int beg = row_ptr[d];
    const int end = row_ptr[d + 1];

    float4 acc = make_float4(0.f, 0.f, 0.f, 0.f);
    const __half* __restrict__ G = g_half;

    int j = beg;
    for (; j + 8 <= end; j += 8) {
        int2 e[8];
#pragma unroll
        for (int q = 0; q < 8; q++) e[q] = __ldg(&edge_sorted[j + q]);
        uint2 gv[8];
#pragma unroll
        for (int q = 0; q < 8; q++)
            gv[q] = *(const uint2*)(G + (size_t)e[q].x * 128 + lane * 4);
#pragma unroll
        for (int q = 0; q < 8; q++) {
            const float w = __int_as_float(e[q].y);
            const float2 f0 = __half22float2(*reinterpret_cast<const __half2*>(&gv[q].x));
            const float2 f1 = __half22float2(*reinterpret_cast<const __half2*>(&gv[q].y));
            acc.x += w * f0.x; acc.y += w * f0.y;
            acc.z += w * f1.x; acc.w += w * f1.y;
        }
    }
    for (; j < end; j++) {
        const int2 e = __ldg(&edge_sorted[j]);
        const float w = __int_as_float(e.y);
        const uint2 gv = *(const uint2*)(G + (size_t)e.x * 128 + lane * 4);
        const float2 f0 = __half22float2(*reinterpret_cast<const __half2*>(&gv.x));
        const float2 f1 = __half22float2(*reinterpret_cast<const __half2*>(&gv.y));
        acc.x += w * f0.x; acc.y += w * f0.y;
        acc.z += w * f1.x; acc.w += w * f1.y;
    }

    // epilogue: h = relu(acc + b1) * mask * 2   (precomputed mask bits)
    const float4 bv = *(const float4*)(b1 + lane * 4);
    const uint32_t mword = __ldg(&mask_buf[(uint32_t)d * 4u + (lane >> 3)]);
    const uint32_t mb = (mword >> ((lane & 7) * 4)) & 0xFu;

    float v0 = fmaxf(acc.x + bv.x, 0.f);
    float v1 = fmaxf(acc.y + bv.y, 0.f);
    float v2 = fmaxf(acc.z + bv.z, 0.f);
    float v3 = fmaxf(acc.w + bv.w, 0.f);
    v0 = (mb & 1u) ? 0.f : v0 * 2.f;
    v1 = (mb & 2u) ? 0.f : v1 * 2.f;
    v2 = (mb & 4u) ? 0.f : v2 * 2.f;
    v3 = (mb & 8u) ? 0.f : v3 * 2.f;

    uint2 o;
    const __half2 h0 = __floats2half2_rn(v0, v1);
    const __half2 h1 = __floats2half2_rn(v2, v3);
    o.x = *reinterpret_cast<const uint32_t*>(&h0);
    o.y = *reinterpret_cast<const uint32_t*>(&h1);
    *(uint2*)(h_half + (size_t)d * 128 + lane * 4) = o;
}

// ===========================================================================
// SpMM2 (CSR, F=64, fp16 gather) fused with +b2. Lane owns 2 features.
// ===========================================================================
__global__ void __launch_bounds__(256)
spmm2_fused(const float* __restrict__ b2, float* __restrict__ out, int N)
{
    const int d    = (blockIdx.x * blockDim.x + threadIdx.x) >> 5;
    const int lane = threadIdx.x & 31;
    if (d >= N) return;

    const int beg = row_ptr[d];
    const int end = row_ptr[d + 1];

    float2 acc = make_float2(0.f, 0.f);
    const __half* __restrict__ P = p_half;

    int j = beg;
    for (; j + 8 <= end; j += 8) {
        int2 e[8];
#pragma unroll
        for (int q = 0; q < 8; q++) e[q] = __ldg(&edge_sorted[j + q]);
        __half2 pv[8];
#pragma unroll
        for (int q = 0; q < 8; q++)
            pv[q] = *(const __half2*)(P + (size_t)e[q].x * 64 + lane * 2);
#pragma unroll
        for (int q = 0; q < 8; q++) {
            const float w = __int_as_float(e[q].y);
            const float2 f = __half22float2(pv[q]);
            acc.x += w * f.x; acc.y += w * f.y;
        }
    }
    for (; j < end; j++) {
        const int2 e = __ldg(&edge_sorted[j]);
        const float w = __int_as_float(e.y);
        const float2 f = __half22float2(*(const __half2*)(P + (size_t)e.x * 64 + lane * 2));
        acc.x += w * f.x; acc.y += w * f.y;
    }

    const float2 bv = *(const float2*)(b2 + lane * 2);
    float2 o; o.x = acc.x + bv.x; o.y = acc.y + bv.y;
    *(float2*)(out + (size_t)d * 64 + lane * 2) = o;
}

// ---------------------------------------------------------------------------
// kernel_launch
// inputs: x, edge_weight, W1, b1, W2, b2, src, dst, n_nodes
// Fork: main = gemm1, s2 = CSR build, s3 = mask gen. Join before spmm1.
// ---------------------------------------------------------------------------
extern "C" void kernel_launch(void* const* d_in, const int* in_sizes, int n_in,
                              void* d_out, int out_size)
{
    const float* x   = (const float*)d_in[0];
    const float* ew  = (const float*)d_in[1];
    const float* W1  = (const float*)d_in[2];
    const float* b1  = (const float*)d_in[3];
    const float* W2  = (const float*)d_in[4];
    const float* b2  = (const float*)d_in[5];
    const int*   src = (const int*)d_in[6];
    const int*   dst = (const int*)d_in[7];

    const int N = in_sizes[0] / 128;
    const int E = in_sizes[1];
    float* out = (float*)d_out;

    const int nchunks = (N + SCAN_CHUNK - 1) / SCAN_CHUNK;

    static cudaStream_t s2 = nullptr, s3 = nullptr;
    static cudaEvent_t  ev_fork = nullptr, ev_join2 = nullptr, ev_join3 = nullptr;
    static bool tried = false;
    if (!tried) {
        tried = true;
        if (cudaStreamCreateWithFlags(&s2, cudaStreamNonBlocking) != cudaSuccess) s2 = nullptr;
        if (cudaStreamCreateWithFlags(&s3, cudaStreamNonBlocking) != cudaSuccess) s3 = nullptr;
        if (s2) {
            cudaEventCreateWithFlags(&ev_fork, cudaEventDisableTiming);
            cudaEventCreateWithFlags(&ev_join2, cudaEventDisableTiming);
        }
        if (s3) cudaEventCreateWithFlags(&ev_join3, cudaEventDisableTiming);
    }

    cudaStream_t cs = s2 ? s2 : (cudaStream_t)0;   // CSR stream
    cudaStream_t ms = s3 ? s3 : (cudaStream_t)0;   // mask stream

    if (s2 || s3) {
        if (!ev_fork) cudaEventCreateWithFlags(&ev_fork, cudaEventDisableTiming);
        cudaEventRecord(ev_fork, 0);
        if (s2) cudaStreamWaitEvent(s2, ev_fork, 0);
        if (s3) cudaStreamWaitEvent(s3, ev_fork, 0);
    }

    // --- mask gen on s3 (no inputs; pure ALU, overlaps gemm1 + CSR) ---
    k_mask<<<(N * 128 + 255) / 256, 256, 0, ms>>>(N * 128);
    if (s3) cudaEventRecord(ev_join3, s3);

    // --- CSR build on s2 ---
    k_zero_deg   <<<(N + 255) / 256, 256, 0, cs>>>(N);
    k_hist       <<<(E + 255) / 256, 256, 0, cs>>>(dst, E);
    k_part_sums  <<<nchunks, 256, 0, cs>>>(N);
    k_scan_parts <<<1, 128, 0, cs>>>(nchunks, N, E);
    k_scan_chunks<<<nchunks, SCAN_CHUNK, 0, cs>>>(N);
    k_scatter    <<<(E + 255) / 256, 256, 0, cs>>>(src, dst, ew, E);
    if (s2) cudaEventRecord(ev_join2, s2);

    // --- gemm1 on main stream, overlapped with CSR + mask ---
    gemm1_k128<<<(N + 127) / 128, 256>>>(x, W1, N);

    if (s2) cudaStreamWaitEvent((cudaStream_t)0, ev_join2, 0);
    if (s3) cudaStreamWaitEvent((cudaStream_t)0, ev_join3, 0);

    // h = relu(spmm(A, g) + b1) * mask * 2    (fp16 in, fp16 out, mask bits)
    spmm1_fused<<<(N * 32 + 255) / 256, 256>>>(b1, N);
    // p = h @ W2                               (fp16 in/out, fp32 math)
    gemm2_k128<<<(N + 127) / 128, 256>>>(W2, N);
    // out = spmm(A, p) + b2
    spmm2_fused<<<(N * 32 + 255) / 256, 256>>>(b2, out, N);
}

// round 13
// speedup vs baseline: 1.1862x; 1.0562x over previous
#include <cuda_runtime.h>
#include <cuda_fp16.h>
#include <cstdint>
#include <cstddef>

// ---------------------------------------------------------------------------
// Fixed shapes: N=100000, E=1600000, F 128 -> 128 -> 64
// ---------------------------------------------------------------------------
#define MAX_N 100000
#define MAX_E 1600000
#define SCAN_CHUNK 1024
#define MAX_CHUNKS ((MAX_N + SCAN_CHUNK - 1) / SCAN_CHUNK)   // 98

// Scratch (device BSS — no allocation inside kernel_launch)
__device__ __half g_half[(size_t)MAX_N * 128];   // x @ W1, fp16
__device__ __half h_half[(size_t)MAX_N * 128];   // relu+bias+dropout, fp16
__device__ __half p_half[(size_t)MAX_N * 64];    // h @ W2, fp16

__device__ int   deg_buf   [MAX_N];
__device__ int   row_ptr   [MAX_N + 1];
__device__ int   cursor    [MAX_N];
__device__ int   part_buf  [MAX_CHUNKS];
__device__ int   partoff   [MAX_CHUNKS];
__device__ int2  edge_sorted[MAX_E];             // packed (src, w_bits)

// ---------------------------------------------------------------------------
// Threefry-2x32, key = (0, 42) — bit-exact replica of jax threefry2x32 core
// ---------------------------------------------------------------------------
__device__ __forceinline__ void threefry_0_42(uint32_t x0, uint32_t x1,
                                              uint32_t& o0, uint32_t& o1)
{
    const uint32_t k0 = 0u, k1 = 42u;
    const uint32_t k2 = k0 ^ k1 ^ 0x1BD11BDAu;
    x0 += k0; x1 += k1;
#define TF_R(r) { x0 += x1; x1 = (x1 << (r)) | (x1 >> (32 - (r))); x1 ^= x0; }
    TF_R(13) TF_R(15) TF_R(26) TF_R(6)   x0 += k1; x1 += k2 + 1u;
    TF_R(17) TF_R(29) TF_R(16) TF_R(24)  x0 += k2; x1 += k0 + 2u;
    TF_R(13) TF_R(15) TF_R(26) TF_R(6)   x0 += k0; x1 += k1 + 3u;
    TF_R(17) TF_R(29) TF_R(16) TF_R(24)  x0 += k1; x1 += k2 + 4u;
    TF_R(13) TF_R(15) TF_R(26) TF_R(6)   x0 += k2; x1 += k0 + 5u;
#undef TF_R
    o0 = x0; o1 = x1;
}

__device__ __forceinline__ bool drop_mask(uint32_t i)
{
    uint32_t o0, o1;
    threefry_0_42(0u, i, o0, o1);
    return ((o0 ^ o1) & 0x80000000u) != 0u;   // true = drop (XOR-fold)
}

// ---------------------------------------------------------------------------
// Packed fp32x2 FMA helpers (FFMA2)
// ---------------------------------------------------------------------------
#define FMA2(acc_, a_, b_) \
    asm("fma.rn.f32x2 %0, %1, %2, %0;" : "+l"(acc_) : "l"(a_), "l"(b_))

__device__ __forceinline__ unsigned long long dup2(float a)
{
    unsigned long long r;
    asm("mov.b64 %0, {%1, %1};" : "=l"(r) : "r"(__float_as_uint(a)));
    return r;
}

__device__ __forceinline__ uint32_t pack_half2_from(unsigned long long v64)
{
    const float lo = __uint_as_float((unsigned)(v64 & 0xffffffffu));
    const float hi = __uint_as_float((unsigned)(v64 >> 32));
    const __half2 h = __floats2half2_rn(lo, hi);
    return *reinterpret_cast<const uint32_t*>(&h);
}

// ===========================================================================
// GEMM1 (FFMA2):  g_half[M,128] = x[M,128] @ W1[128,128], fp16 output
// ===========================================================================
__global__ void __launch_bounds__(256, 2)
gemm1_k128(const float* __restrict__ A, const float* __restrict__ B, int M)
{
    constexpr int BN = 128;
    __shared__ __align__(16) float As[2][16 * 128];
    __shared__ __align__(16) float Bs[2][16 * BN];

    const int tid = threadIdx.x;
    const int tx  = tid & 15;
    const int ty  = tid >> 4;
    const int m0  = blockIdx.x * 128;
    const int lr  = tid >> 2;
    const int lc  = tid & 3;

    unsigned long long acc[8][4];
#pragma unroll
    for (int r = 0; r < 8; r++)
#pragma unroll
        for (int j = 0; j < 4; j++) acc[r][j] = 0ull;

    auto loadTiles = [&](int buf, int kk) {
#pragma unroll
        for (int rr = 0; rr < 2; rr++) {
            int row = m0 + lr + rr * 64;
            if (row > M - 1) row = M - 1;
            const float4 v = *(const float4*)(A + (size_t)row * 128 + kk + lc * 4);
            float* d = &As[buf][0];
            const int mi = lr + rr * 64;
            d[(lc * 4 + 0) * 128 + mi] = v.x;
            d[(lc * 4 + 1) * 128 + mi] = v.y;
            d[(lc * 4 + 2) * 128 + mi] = v.z;
            d[(lc * 4 + 3) * 128 + mi] = v.w;
        }
#pragma unroll
        for (int i = 0; i < 2; i++) {
            const int idx = (i * 256 + tid) * 4;
            *(float4*)&Bs[buf][idx] = *(const float4*)(B + kk * BN + idx);
        }
    };

    loadTiles(0, 0);
    __syncthreads();

#pragma unroll 1
    for (int kk = 0; kk < 128; kk += 16) {
        const int cur = (kk >> 4) & 1;
        if (kk + 16 < 128) loadTiles(cur ^ 1, kk + 16);
#pragma unroll
        for (int k = 0; k < 16; k++) {
            const float4 a0 = *(const float4*)&As[cur][k * 128 + ty * 4];
            const float4 a1 = *(const float4*)&As[cur][k * 128 + ty * 4 + 64];
            unsigned long long a2[8];
            a2[0] = dup2(a0.x); a2[1] = dup2(a0.y);
            a2[2] = dup2(a0.z); a2[3] = dup2(a0.w);
            a2[4] = dup2(a1.x); a2[5] = dup2(a1.y);
            a2[6] = dup2(a1.z); a2[7] = dup2(a1.w);
#pragma unroll
            for (int g = 0; g < 2; g++) {
                const double2 b = *(const double2*)&Bs[cur][k * BN + tx * 4 + g * 64];
                const unsigned long long bl = __double_as_longlong(b.x);
                const unsigned long long bh = __double_as_longlong(b.y);
#pragma unroll
                for (int r = 0; r < 8; r++) {
                    FMA2(acc[r][2 * g + 0], a2[r], bl);
                    FMA2(acc[r][2 * g + 1], a2[r], bh);
                }
            }
        }
        __syncthreads();
    }

#pragma unroll
    for (int r = 0; r < 8; r++) {
        const int row = m0 + ty * 4 + (r >> 2) * 64 + (r & 3);
        if (row < M) {
#pragma unroll
            for (int g = 0; g < 2; g++) {
                uint2 o;
                o.x = pack_half2_from(acc[r][2 * g + 0]);
                o.y = pack_half2_from(acc[r][2 * g + 1]);
                *(uint2*)(g_half + (size_t)row * 128 + tx * 4 + g * 64) = o;
            }
        }
    }
}

// ===========================================================================
// GEMM2 (FFMA2):  p_half[M,64] = h_half[M,128] @ W2[128,64]
// A is fp16 (converted to fp32 in SMEM staging), math fp32.
// ===========================================================================
__global__ void __launch_bounds__(256, 2)
gemm2_k128(const float* __restrict__ B, int M)
{
    constexpr int BN = 64;
    const __half* __restrict__ A = h_half;

    __shared__ __align__(16) float As[2][16 * 128];
    __shared__ __align__(16) float Bs[2][16 * BN];

    const int tid = threadIdx.x;
    const int tx  = tid & 15;
    const int ty  = tid >> 4;
    const int m0  = blockIdx.x * 128;
    const int lr  = tid >> 2;
    const int lc  = tid & 3;

    unsigned long long acc[8][2];
#pragma unroll
    for (int r = 0; r < 8; r++) { acc[r][0] = 0ull; acc[r][1] = 0ull; }

    auto loadTiles = [&](int buf, int kk) {
#pragma unroll
        for (int rr = 0; rr < 2; rr++) {
            int row = m0 + lr + rr * 64;
            if (row > M - 1) row = M - 1;
            const uint2 hv = *(const uint2*)(A + (size_t)row * 128 + kk + lc * 4);
            const float2 f0 = __half22float2(*reinterpret_cast<const __half2*>(&hv.x));
            const float2 f1 = __half22float2(*reinterpret_cast<const __half2*>(&hv.y));
            float* d = &As[buf][0];
            const int mi = lr + rr * 64;
            d[(lc * 4 + 0) * 128 + mi] = f0.x;
            d[(lc * 4 + 1) * 128 + mi] = f0.y;
            d[(lc * 4 + 2) * 128 + mi] = f1.x;
            d[(lc * 4 + 3) * 128 + mi] = f1.y;
        }
        {
            const int idx = tid * 4;
            if (idx < 16 * BN)
                *(float4*)&Bs[buf][idx] = *(const float4*)(B + kk * BN + idx);
        }
    };

    loadTiles(0, 0);
    __syncthreads();

#pragma unroll 1
    for (int kk = 0; kk < 128; kk += 16) {
        const int cur = (kk >> 4) & 1;
        if (kk + 16 < 128) loadTiles(cur ^ 1, kk + 16);
#pragma unroll
        for (int k = 0; k < 16; k++) {
            const float4 a0 = *(const float4*)&As[cur][k * 128 + ty * 4];
            const float4 a1 = *(const float4*)&As[cur][k * 128 + ty * 4 + 64];
            unsigned long long a2[8];
            a2[0] = dup2(a0.x); a2[1] = dup2(a0.y);
            a2[2] = dup2(a0.z); a2[3] = dup2(a0.w);
            a2[4] = dup2(a1.x); a2[5] = dup2(a1.y);
            a2[6] = dup2(a1.z); a2[7] = dup2(a1.w);
            const double2 b = *(const double2*)&Bs[cur][k * BN + tx * 4];
            const unsigned long long bl = __double_as_longlong(b.x);
            const unsigned long long bh = __double_as_longlong(b.y);
#pragma unroll
            for (int r = 0; r < 8; r++) {
                FMA2(acc[r][0], a2[r], bl);
                FMA2(acc[r][1], a2[r], bh);
            }
        }
        __syncthreads();
    }

#pragma unroll
    for (int r = 0; r < 8; r++) {
        const int row = m0 + ty * 4 + (r >> 2) * 64 + (r & 3);
        if (row < M) {
            uint2 o;
            o.x = pack_half2_from(acc[r][0]);
            o.y = pack_half2_from(acc[r][1]);
            *(uint2*)(p_half + (size_t)row * 64 + tx * 4) = o;
        }
    }
}

// ===========================================================================
// CSR build: deg -> scan -> scatter (packed payload)
// ===========================================================================
__global__ void k_zero_deg(int N)
{
    const int i = blockIdx.x * blockDim.x + threadIdx.x;
    if (i < N) deg_buf[i] = 0;
}

__global__ void k_hist(const int* __restrict__ dst, int E)
{
    const int e = blockIdx.x * blockDim.x + threadIdx.x;
    if (e < E) atomicAdd(&deg_buf[dst[e]], 1);
}

__global__ void k_part_sums(int N)
{
    __shared__ int sm[256];
    const int b = blockIdx.x, t = threadIdx.x;
    int s = 0;
#pragma unroll
    for (int k = 0; k < 4; k++) {
        const int i = b * SCAN_CHUNK + k * 256 + t;
        if (i < N) s += deg_buf[i];
    }
    sm[t] = s; __syncthreads();
    for (int off = 128; off > 0; off >>= 1) {
        if (t < off) sm[t] += sm[t + off];
        __syncthreads();
    }
    if (t == 0) part_buf[b] = sm[0];
}

__global__ void k_scan_parts(int nchunks, int N, int E)
{
    __shared__ int sm[128];
    const int t = threadIdx.x;
    const int v = (t < nchunks) ? part_buf[t] : 0;
    sm[t] = v; __syncthreads();
#pragma unroll
    for (int off = 1; off < 128; off <<= 1) {
        const int x = (t >= off) ? sm[t - off] : 0;
        __syncthreads();
        sm[t] += x;
        __syncthreads();
    }
    if (t < nchunks) partoff[t] = sm[t] - v;
    if (t == 0) row_ptr[N] = E;
}

__global__ void k_scan_chunks(int N)
{
    __shared__ int sm[SCAN_CHUNK];
    const int b = blockIdx.x, t = threadIdx.x;
    const int i = b * SCAN_CHUNK + t;
    const int v = (i < N) ? deg_buf[i] : 0;
    sm[t] = v; __syncthreads();
#pragma unroll
    for (int off = 1; off < SCAN_CHUNK; off <<= 1) {
        const int x = (t >= off) ? sm[t - off] : 0;
        __syncthreads();
        sm[t] += x;
        __syncthreads();
    }
    if (i < N) {
        const int ex = sm[t] - v + partoff[b];
        row_ptr[i] = ex;
        cursor[i]  = ex;
    }
}

__global__ void k_scatter(const int* __restrict__ src, const int* __restrict__ dst,
                          const float* __restrict__ ew, int E)
{
    const int e = blockIdx.x * blockDim.x + threadIdx.x;
    if (e >= E) return;
    const int pos = atomicAdd(&cursor[dst[e]], 1);
    int2 pkt;
    pkt.x = src[e];
    pkt.y = __float_as_int(ew[e]);
    edge_sorted[pos] = pkt;
}

// ===========================================================================
// SpMM1 (CSR, F=128, fp16 gather) + bias/relu/dropout epilogue (fp16 out).
// Threefry in the epilogue — hidden under gather latency (R9/R12 evidence).
// ===========================================================================
__global__ void __launch_bounds__(256)
spmm1_fused(const float* __restrict__ b1, int N)
{
    const int d    = (blockIdx.x * blockDim.x + threadIdx.x) >> 5;
    const int lane = threadIdx.x & 31;
    if (d >= N) return;

    const int beg = row_ptr[d];
    const int end = row_ptr[d + 1];

    float4 acc = make_float4(0.f, 0.f, 0.f, 0.f);
    const __half* __restrict__ G = g_half;

    int j = beg;
    for (; j + 8 <= end; j += 8) {
        int2 e[8];
#pragma unroll
        for (int q = 0; q < 8; q++) e[q] = __ldg(&edge_sorted[j + q]);
        uint2 gv[8];
#pragma unroll
        for (int q = 0; q < 8; q++)
            gv[q] = *(const uint2*)(G + (size_t)e[q].x * 128 + lane * 4);
#pragma unroll
        for (int q = 0; q < 8; q++) {
            const float w = __int_as_float(e[q].y);
            const float2 f0 = __half22float2(*reinterpret_cast<const __half2*>(&gv[q].x));
            const float2 f1 = __half22float2(*reinterpret_cast<const __half2*>(&gv[q].y));
            acc.x += w * f0.x; acc.y += w * f0.y;
            acc.z += w * f1.x; acc.w += w * f1.y;
        }
    }
    for (; j < end; j++) {
        const int2 e = __ldg(&edge_sorted[j]);
        const float w = __int_as_float(e.y);
        const uint2 gv = *(const uint2*)(G + (size_t)e.x * 128 + lane * 4);
        const float2 f0 = __half22float2(*reinterpret_cast<const __half2*>(&gv.x));
        const float2 f1 = __half22float2(*reinterpret_cast<const __half2*>(&gv.y));
        acc.x += w * f0.x; acc.y += w * f0.y;
        acc.z += w * f1.x; acc.w += w * f1.y;
    }

    // epilogue: h = relu(acc + b1) * mask * 2   (fp16 output)
    const float4 bv = *(const float4*)(b1 + lane * 4);
    const uint32_t base = (uint32_t)d * 128u + (uint32_t)lane * 4u;

    float v0 = fmaxf(acc.x + bv.x, 0.f);
    float v1 = fmaxf(acc.y + bv.y, 0.f);
    float v2 = fmaxf(acc.z + bv.z, 0.f);
    float v3 = fmaxf(acc.w + bv.w, 0.f);
    v0 = drop_mask(base + 0u) ? 0.f : v0 * 2.f;
    v1 = drop_mask(base + 1u) ? 0.f : v1 * 2.f;
    v2 = drop_mask(base + 2u) ? 0.f : v2 * 2.f;
    v3 = drop_mask(base + 3u) ? 0.f : v3 * 2.f;

    uint2 o;
    const __half2 h0 = __floats2half2_rn(v0, v1);
    const __half2 h1 = __floats2half2_rn(v2, v3);
    o.x = *reinterpret_cast<const uint32_t*>(&h0);
    o.y = *reinterpret_cast<const uint32_t*>(&h1);
    *(uint2*)(h_half + (size_t)d * 128 + lane * 4) = o;
}

// ===========================================================================
// SpMM2 (CSR, F=64, fp16 gather) fused with +b2. Lane owns 2 features.
// ===========================================================================
__global__ void __launch_bounds__(256)
spmm2_fused(const float* __restrict__ b2, float* __restrict__ out, int N)
{
    const int d    = (blockIdx.x * blockDim.x + threadIdx.x) >> 5;
    const int lane = threadIdx.x & 31;
    if (d >= N) return;

    const int beg = row_ptr[d];
    const int end = row_ptr[d + 1];

    float2 acc = make_float2(0.f, 0.f);
    const __half* __restrict__ P = p_half;

    int j = beg;
    for (; j + 8 <= end; j += 8) {
        int2 e[8];
#pragma unroll
        for (int q = 0; q < 8; q++) e[q] = __ldg(&edge_sorted[j + q]);
        __half2 pv[8];
#pragma unroll
        for (int q = 0; q < 8; q++)
            pv[q] = *(const __half2*)(P + (size_t)e[q].x * 64 + lane * 2);
#pragma unroll
        for (int q = 0; q < 8; q++) {
            const float w = __int_as_float(e[q].y);
            const float2 f = __half22float2(pv[q]);
            acc.x += w * f.x; acc.y += w * f.y;
        }
    }
    for (; j < end; j++) {
        const int2 e = __ldg(&edge_sorted[j]);
        const float w = __int_as_float(e.y);
        const float2 f = __half22float2(*(const __half2*)(P + (size_t)e.x * 64 + lane * 2));
        acc.x += w * f.x; acc.y += w * f.y;
    }

    const float2 bv = *(const float2*)(b2 + lane * 2);
    float2 o; o.x = acc.x + bv.x; o.y = acc.y + bv.y;
    *(float2*)(out + (size_t)d * 64 + lane * 2) = o;
}

// ---------------------------------------------------------------------------
// kernel_launch
// inputs: x, edge_weight, W1, b1, W2, b2, src, dst, n_nodes
// Fork: main = gemm1, s2 = CSR build. Join before spmm1.  (R10 structure)
// ---------------------------------------------------------------------------
extern "C" void kernel_launch(void* const* d_in, const int* in_sizes, int n_in,
                              void* d_out, int out_size)
{
    const float* x   = (const float*)d_in[0];
    const float* ew  = (const float*)d_in[1];
    const float* W1  = (const float*)d_in[2];
    const float* b1  = (const float*)d_in[3];
    const float* W2  = (const float*)d_in[4];
    const float* b2  = (const float*)d_in[5];
    const int*   src = (const int*)d_in[6];
    const int*   dst = (const int*)d_in[7];

    const int N = in_sizes[0] / 128;
    const int E = in_sizes[1];
    float* out = (float*)d_out;

    const int nchunks = (N + SCAN_CHUNK - 1) / SCAN_CHUNK;

    static cudaStream_t s2 = nullptr;
    static cudaEvent_t  ev_fork = nullptr, ev_join = nullptr;
    static bool tried = false;
    if (!tried) {
        tried = true;
        if (cudaStreamCreateWithFlags(&s2, cudaStreamNonBlocking) != cudaSuccess) s2 = nullptr;
        if (s2) {
            cudaEventCreateWithFlags(&ev_fork, cudaEventDisableTiming);
            cudaEventCreateWithFlags(&ev_join, cudaEventDisableTiming);
        }
    }

    cudaStream_t cs = s2 ? s2 : (cudaStream_t)0;

    if (s2) {
        cudaEventRecord(ev_fork, 0);
        cudaStreamWaitEvent(s2, ev_fork, 0);
    }

    // --- CSR build on secondary stream (independent of gemm1) ---
    k_zero_deg   <<<(N + 255) / 256, 256, 0, cs>>>(N);
    k_hist       <<<(E + 255) / 256, 256, 0, cs>>>(dst, E);
    k_part_sums  <<<nchunks, 256, 0, cs>>>(N);
    k_scan_parts <<<1, 128, 0, cs>>>(nchunks, N, E);
    k_scan_chunks<<<nchunks, SCAN_CHUNK, 0, cs>>>(N);
    k_scatter    <<<(E + 255) / 256, 256, 0, cs>>>(src, dst, ew, E);

    if (s2) cudaEventRecord(ev_join, s2);

    // --- gemm1 on main stream, overlapped with CSR build ---
    gemm1_k128<<<(N + 127) / 128, 256>>>(x, W1, N);

    if (s2) cudaStreamWaitEvent((cudaStream_t)0, ev_join, 0);

    // h = relu(spmm(A, g) + b1) * mask * 2    (fp16 in/out, threefry in epilogue)
    spmm1_fused<<<(N * 32 + 255) / 256, 256>>>(b1, N);
    // p = h @ W2                               (fp16 in/out, fp32 math)
    gemm2_k128<<<(N + 127) / 128, 256>>>(W2, N);
    // out = spmm(A, p) + b2
    spmm2_fused<<<(N * 32 + 255) / 256, 256>>>(b2, out, N);
}

// round 14
// speedup vs baseline: 1.2891x; 1.0867x over previous
#include <cuda_runtime.h>
#include <cuda_fp16.h>
#include <mma.h>
#include <cstdint>
#include <cstddef>

using namespace nvcuda;

// ---------------------------------------------------------------------------
// Fixed shapes: N=100000, E=1600000, F 128 -> 128 -> 64
// ---------------------------------------------------------------------------
#define MAX_N 100000
#define MAX_E 1600000
#define SCAN_CHUNK 1024
#define MAX_CHUNKS ((MAX_N + SCAN_CHUNK - 1) / SCAN_CHUNK)   // 98

// Scratch (device BSS — no allocation inside kernel_launch)
__device__ __half g_half[(size_t)MAX_N * 128];   // x @ W1, fp16
__device__ __half h_half[(size_t)MAX_N * 128];   // relu+bias+dropout, fp16
__device__ __half p_half[(size_t)MAX_N * 64];    // h @ W2, fp16
__device__ __align__(16) __half w1_fp16[128 * 128];  // W1 pre-converted

__device__ int   deg_buf   [MAX_N];
__device__ int   row_ptr   [MAX_N + 1];
__device__ int   cursor    [MAX_N];
__device__ int   part_buf  [MAX_CHUNKS];
__device__ int   partoff   [MAX_CHUNKS];
__device__ int2  edge_sorted[MAX_E];             // packed (src, w_bits)

// ---------------------------------------------------------------------------
// Threefry-2x32, key = (0, 42) — bit-exact replica of jax threefry2x32 core
// ---------------------------------------------------------------------------
__device__ __forceinline__ void threefry_0_42(uint32_t x0, uint32_t x1,
                                              uint32_t& o0, uint32_t& o1)
{
    const uint32_t k0 = 0u, k1 = 42u;
    const uint32_t k2 = k0 ^ k1 ^ 0x1BD11BDAu;
    x0 += k0; x1 += k1;
#define TF_R(r) { x0 += x1; x1 = (x1 << (r)) | (x1 >> (32 - (r))); x1 ^= x0; }
    TF_R(13) TF_R(15) TF_R(26) TF_R(6)   x0 += k1; x1 += k2 + 1u;
    TF_R(17) TF_R(29) TF_R(16) TF_R(24)  x0 += k2; x1 += k0 + 2u;
    TF_R(13) TF_R(15) TF_R(26) TF_R(6)   x0 += k0; x1 += k1 + 3u;
    TF_R(17) TF_R(29) TF_R(16) TF_R(24)  x0 += k1; x1 += k2 + 4u;
    TF_R(13) TF_R(15) TF_R(26) TF_R(6)   x0 += k2; x1 += k0 + 5u;
#undef TF_R
    o0 = x0; o1 = x1;
}

__device__ __forceinline__ bool drop_mask(uint32_t i)
{
    uint32_t o0, o1;
    threefry_0_42(0u, i, o0, o1);
    return ((o0 ^ o1) & 0x80000000u) != 0u;   // true = drop (XOR-fold)
}

// ---------------------------------------------------------------------------
// Packed fp32x2 FMA helpers (FFMA2) — gemm2
// ---------------------------------------------------------------------------
#define FMA2(acc_, a_, b_) \
    asm("fma.rn.f32x2 %0, %1, %2, %0;" : "+l"(acc_) : "l"(a_), "l"(b_))

__device__ __forceinline__ unsigned long long dup2(float a)
{
    unsigned long long r;
    asm("mov.b64 %0, {%1, %1};" : "=l"(r) : "r"(__float_as_uint(a)));
    return r;
}

__device__ __forceinline__ uint32_t pack_half2_from(unsigned long long v64)
{
    const float lo = __uint_as_float((unsigned)(v64 & 0xffffffffu));
    const float hi = __uint_as_float((unsigned)(v64 >> 32));
    const __half2 h = __floats2half2_rn(lo, hi);
    return *reinterpret_cast<const uint32_t*>(&h);
}

// ===========================================================================
// Prep: W1 fp32 -> fp16 global image (once per launch; tiny)
// ===========================================================================
__global__ void k_prep_w1(const float* __restrict__ W1)
{
    const int i = blockIdx.x * blockDim.x + threadIdx.x;
    if (i < 128 * 128) w1_fp16[i] = __float2half_rn(W1[i]);
}

// ===========================================================================
// GEMM1 (wmma fp16, single pass): g_half[M,128] = x[M,128] @ W1[128,128]
// CTA = 128 rows, 256 threads = 8 warps (2x4). Warp tile 64x32 (4x2 frags).
// A tile converted to SMEM fp16; B copied from pre-converted global image.
// All operands SMEM-resident during MMA. fp32 accumulate.
// ===========================================================================
#define G1_LD  136                                     // anti-conflict pad
#define G1_A_OFF   0
#define G1_B_OFF   (128 * G1_LD)                       // halfs
#define G1_SMEM_HALFS (2 * 128 * G1_LD)                // 34816 halfs
#define G1_STAGE_OFF  (G1_SMEM_HALFS * 2)              // bytes: staging after A/B
#define G1_SMEM_BYTES (G1_SMEM_HALFS * 2 + 8 * 16 * 16 * 4)   // 69632 + 8192

__global__ void __launch_bounds__(256, 2)
gemm1_wmma(const float* __restrict__ x, int M)
{
    extern __shared__ __align__(16) char smem_raw[];
    __half* Ah = (__half*)smem_raw;                    // [128][G1_LD]
    __half* Bh = Ah + G1_B_OFF;                        // [128][G1_LD] (k-major)
    float*  stage = (float*)(smem_raw + G1_STAGE_OFF); // [8][16*16]

    const int tid = threadIdx.x;
    const int wid = tid >> 5;
    const int lane = tid & 31;
    const int m0  = blockIdx.x * 128;
    const int warp_m = wid >> 2;   // 0..1
    const int warp_n = wid & 3;    // 0..3

    // Load + convert x tile (128 rows x 128 fp32) -> Ah fp16
    for (int i = tid; i < 128 * 32; i += 256) {        // i indexes float4
        const int row = i >> 5;
        const int c4  = (i & 31) * 4;
        int grow = m0 + row;
        if (grow > M - 1) grow = M - 1;                // clamp; never stored
        const float4 v = __ldg((const float4*)(x + (size_t)grow * 128 + c4));
        const __half2 h0 = __floats2half2_rn(v.x, v.y);
        const __half2 h1 = __floats2half2_rn(v.z, v.w);
        *(__half2*)(Ah + row * G1_LD + c4)     = h0;
        *(__half2*)(Ah + row * G1_LD + c4 + 2) = h1;
    }
    // Copy W1 fp16 image -> Bh  (128 k-rows x 128 n, uint4 = 8 halfs)
    for (int i = tid; i < 128 * 16; i += 256) {
        const int row = i >> 4;
        const int c8  = (i & 15) * 8;
        *(uint4*)(Bh + row * G1_LD + c8) =
            *(const uint4*)(w1_fp16 + row * 128 + c8);
    }
    __syncthreads();

    wmma::fragment<wmma::accumulator, 16, 16, 16, float> acc[4][2];
#pragma unroll
    for (int mf = 0; mf < 4; mf++)
#pragma unroll
        for (int nf = 0; nf < 2; nf++)
            wmma::fill_fragment(acc[mf][nf], 0.0f);

#pragma unroll
    for (int ks = 0; ks < 8; ks++) {
        wmma::fragment<wmma::matrix_b, 16, 16, 16, __half, wmma::row_major> bf[2];
#pragma unroll
        for (int nf = 0; nf < 2; nf++)
            wmma::load_matrix_sync(bf[nf],
                Bh + ks * 16 * G1_LD + warp_n * 32 + nf * 16, G1_LD);
#pragma unroll
        for (int mf = 0; mf < 4; mf++) {
            wmma::fragment<wmma::matrix_a, 16, 16, 16, __half, wmma::row_major> af;
            wmma::load_matrix_sync(af,
                Ah + (warp_m * 64 + mf * 16) * G1_LD + ks * 16, G1_LD);
#pragma unroll
            for (int nf = 0; nf < 2; nf++)
                wmma::mma_sync(acc[mf][nf], af, bf[nf], acc[mf][nf]);
        }
    }

    // Epilogue: per-warp 16x16 float staging -> packed fp16 global writes.
    float* st = stage + wid * 256;
#pragma unroll
    for (int mf = 0; mf < 4; mf++) {
        const int r0 = m0 + warp_m * 64 + mf * 16;
        const bool valid = (r0 + 16 <= M);             // M % 16 == 0
#pragma unroll
        for (int nf = 0; nf < 2; nf++) {
            wmma::store_matrix_sync(st, acc[mf][nf], 16, wmma::mem_row_major);
            __syncwarp();
            if (valid) {
                // lane -> (row = lane>>1, 8-col chunk = lane&1)
                const int row = lane >> 1;
                const int c0  = (lane & 1) * 8;
                const float* s = st + row * 16 + c0;
                uint4 o;
                __half2 q0 = __floats2half2_rn(s[0], s[1]);
                __half2 q1 = __floats2half2_rn(s[2], s[3]);
                __half2 q2 = __floats2half2_rn(s[4], s[5]);
                __half2 q3 = __floats2half2_rn(s[6], s[7]);
                o.x = *reinterpret_cast<const uint32_t*>(&q0);
                o.y = *reinterpret_cast<const uint32_t*>(&q1);
                o.z = *reinterpret_cast<const uint32_t*>(&q2);
                o.w = *reinterpret_cast<const uint32_t*>(&q3);
                *(uint4*)(g_half + (size_t)(r0 + row) * 128
                          + warp_n * 32 + nf * 16 + c0) = o;
            }
            __syncwarp();
        }
    }
}

// ===========================================================================
// GEMM2 (FFMA2):  p_half[M,64] = h_half[M,128] @ W2[128,64]  (fp32 math)
// ===========================================================================
__global__ void __launch_bounds__(256, 2)
gemm2_k128(const float* __restrict__ B, int M)
{
    constexpr int BN = 64;
    const __half* __restrict__ A = h_half;

    __shared__ __align__(16) float As[2][16 * 128];
    __shared__ __align__(16) float Bs[2][16 * BN];

    const int tid = threadIdx.x;
    const int tx  = tid & 15;
    const int ty  = tid >> 4;
    const int m0  = blockIdx.x * 128;
    const int lr  = tid >> 2;
    const int lc  = tid & 3;

    unsigned long long acc[8][2];
#pragma unroll
    for (int r = 0; r < 8; r++) { acc[r][0] = 0ull; acc[r][1] = 0ull; }

    auto loadTiles = [&](int buf, int kk) {
#pragma unroll
        for (int rr = 0; rr < 2; rr++) {
            int row = m0 + lr + rr * 64;
            if (row > M - 1) row = M - 1;
            const uint2 hv = *(const uint2*)(A + (size_t)row * 128 + kk + lc * 4);
            const float2 f0 = __half22float2(*reinterpret_cast<const __half2*>(&hv.x));
            const float2 f1 = __half22float2(*reinterpret_cast<const __half2*>(&hv.y));
            float* d = &As[buf][0];
            const int mi = lr + rr * 64;
            d[(lc * 4 + 0) * 128 + mi] = f0.x;
            d[(lc * 4 + 1) * 128 + mi] = f0.y;
            d[(lc * 4 + 2) * 128 + mi] = f1.x;
            d[(lc * 4 + 3) * 128 + mi] = f1.y;
        }
        {
            const int idx = tid * 4;
            if (idx < 16 * BN)
                *(float4*)&Bs[buf][idx] = *(const float4*)(B + kk * BN + idx);
        }
    };

    loadTiles(0, 0);
    __syncthreads();

#pragma unroll 1
    for (int kk = 0; kk < 128; kk += 16) {
        const int cur = (kk >> 4) & 1;
        if (kk + 16 < 128) loadTiles(cur ^ 1, kk + 16);
#pragma unroll
        for (int k = 0; k < 16; k++) {
            const float4 a0 = *(const float4*)&As[cur][k * 128 + ty * 4];
            const float4 a1 = *(const float4*)&As[cur][k * 128 + ty * 4 + 64];
            unsigned long long a2[8];
            a2[0] = dup2(a0.x); a2[1] = dup2(a0.y);
            a2[2] = dup2(a0.z); a2[3] = dup2(a0.w);
            a2[4] = dup2(a1.x); a2[5] = dup2(a1.y);
            a2[6] = dup2(a1.z); a2[7] = dup2(a1.w);
            const double2 b = *(const double2*)&Bs[cur][k * BN + tx * 4];
            const unsigned long long bl = __double_as_longlong(b.x);
            const unsigned long long bh = __double_as_longlong(b.y);
#pragma unroll
            for (int r = 0; r < 8; r++) {
                FMA2(acc[r][0], a2[r], bl);
                FMA2(acc[r][1], a2[r], bh);
            }
        }
        __syncthreads();
    }

#pragma unroll
    for (int r = 0; r < 8; r++) {
        const int row = m0 + ty * 4 + (r >> 2) * 64 + (r & 3);
        if (row < M) {
            uint2 o;
            o.x = pack_half2_from(acc[r][0]);
            o.y = pack_half2_from(acc[r][1]);
            *(uint2*)(p_half + (size_t)row * 64 + tx * 4) = o;
        }
    }
}

// ===========================================================================
// CSR build: deg -> scan -> scatter (packed payload)
// ===========================================================================
__global__ void k_zero_deg(int N)
{
    const int i = blockIdx.x * blockDim.x + threadIdx.x;
    if (i < N) deg_buf[i] = 0;
}

__global__ void k_hist(const int* __restrict__ dst, int E)
{
    const int e = blockIdx.x * blockDim.x + threadIdx.x;
    if (e < E) atomicAdd(&deg_buf[dst[e]], 1);
}

__global__ void k_part_sums(int N)
{
    __shared__ int sm[256];
    const int b = blockIdx.x, t = threadIdx.x;
    int s = 0;
#pragma unroll
    for (int k = 0; k < 4; k++) {
        const int i = b * SCAN_CHUNK + k * 256 + t;
        if (i < N) s += deg_buf[i];
    }
    sm[t] = s; __syncthreads();
    for (int off = 128; off > 0; off >>= 1) {
        if (t < off) sm[t] += sm[t + off];
        __syncthreads();
    }
    if (t == 0) part_buf[b] = sm[0];
}

__global__ void k_scan_parts(int nchunks, int N, int E)
{
    __shared__ int sm[128];
    const int t = threadIdx.x;
    const int v = (t < nchunks) ? part_buf[t] : 0;
    sm[t] = v; __syncthreads();
#pragma unroll
    for (int off = 1; off < 128; off <<= 1) {
        const int x = (t >= off) ? sm[t - off] : 0;
        __syncthreads();
        sm[t] += x;
        __syncthreads();
    }
    if (t < nchunks) partoff[t] = sm[t] - v;
    if (t == 0) row_ptr[N] = E;
}

__global__ void k_scan_chunks(int N)
{
    __shared__ int sm[SCAN_CHUNK];
    const int b = blockIdx.x, t = threadIdx.x;
    const int i = b * SCAN_CHUNK + t;
    const int v = (i < N) ? deg_buf[i] : 0;
    sm[t] = v; __syncthreads();
#pragma unroll
    for (int off = 1; off < SCAN_CHUNK; off <<= 1) {
        const int x = (t >= off) ? sm[t - off] : 0;
        __syncthreads();
        sm[t] += x;
        __syncthreads();
    }
    if (i < N) {
        const int ex = sm[t] - v + partoff[b];
        row_ptr[i] = ex;
        cursor[i]  = ex;
    }
}

__global__ void k_scatter(const int* __restrict__ src, const int* __restrict__ dst,
                          const float* __restrict__ ew, int E)
{
    const int e = blockIdx.x * blockDim.x + threadIdx.x;
    if (e >= E) return;
    const int pos = atomicAdd(&cursor[dst[e]], 1);
    int2 pkt;
    pkt.x = src[e];
    pkt.y = __float_as_int(ew[e]);
    edge_sorted[pos] = pkt;
}

// ===========================================================================
// SpMM1 (CSR, F=128, fp16 gather) + bias/relu/dropout epilogue (fp16 out).
// Threefry in the epilogue — hidden under gather latency (R9/R12 evidence).
// ===========================================================================
__global__ void __launch_bounds__(256)
spmm1_fused(const float* __restrict__ b1, int N)
{
    const int d    = (blockIdx.x * blockDim.x + threadIdx.x) >> 5;
    const int lane = threadIdx.x & 31;
    if (d >= N) return;

    const int beg = row_ptr[d];
    const int end = row_ptr[d + 1];

    float4 acc = make_float4(0.f, 0.f, 0.f, 0.f);
    const __half* __restrict__ G = g_half;

    int j = beg;
    for (; j + 8 <= end; j += 8) {
        int2 e[8];
#pragma unroll
        for (int q = 0; q < 8; q++) e[q] = __ldg(&edge_sorted[j + q]);
        uint2 gv[8];
#pragma unroll
        for (int q = 0; q < 8; q++)
            gv[q] = *(const uint2*)(G + (size_t)e[q].x * 128 + lane * 4);
#pragma unroll
        for (int q = 0; q < 8; q++) {
            const float w = __int_as_float(e[q].y);
            const float2 f0 = __half22float2(*reinterpret_cast<const __half2*>(&gv[q].x));
            const float2 f1 = __half22float2(*reinterpret_cast<const __half2*>(&gv[q].y));
            acc.x += w * f0.x; acc.y += w * f0.y;
            acc.z += w * f1.x; acc.w += w * f1.y;
        }
    }
    for (; j < end; j++) {
        const int2 e = __ldg(&edge_sorted[j]);
        const float w = __int_as_float(e.y);
        const uint2 gv = *(const uint2*)(G + (size_t)e.x * 128 + lane * 4);
        const float2 f0 = __half22float2(*reinterpret_cast<const __half2*>(&gv.x));
        const float2 f1 = __half22float2(*reinterpret_cast<const __half2*>(&gv.y));
        acc.x += w * f0.x; acc.y += w * f0.y;
        acc.z += w * f1.x; acc.w += w * f1.y;
    }

    // epilogue: h = relu(acc + b1) * mask * 2   (fp16 output)
    const float4 bv = *(const float4*)(b1 + lane * 4);
    const uint32_t base = (uint32_t)d * 128u + (uint32_t)lane * 4u;

    float v0 = fmaxf(acc.x + bv.x, 0.f);
    float v1 = fmaxf(acc.y + bv.y, 0.f);
    float v2 = fmaxf(acc.z + bv.z, 0.f);
    float v3 = fmaxf(acc.w + bv.w, 0.f);
    v0 = drop_mask(base + 0u) ? 0.f : v0 * 2.f;
    v1 = drop_mask(base + 1u) ? 0.f : v1 * 2.f;
    v2 = drop_mask(base + 2u) ? 0.f : v2 * 2.f;
    v3 = drop_mask(base + 3u) ? 0.f : v3 * 2.f;

    uint2 o;
    const __half2 h0 = __floats2half2_rn(v0, v1);
    const __half2 h1 = __floats2half2_rn(v2, v3);
    o.x = *reinterpret_cast<const uint32_t*>(&h0);
    o.y = *reinterpret_cast<const uint32_t*>(&h1);
    *(uint2*)(h_half + (size_t)d * 128 + lane * 4) = o;
}

// ===========================================================================
// SpMM2 (CSR, F=64, fp16 gather) fused with +b2. Lane owns 2 features.
// ===========================================================================
__global__ void __launch_bounds__(256)
spmm2_fused(const float* __restrict__ b2, float* __restrict__ out, int N)
{
    const int d    = (blockIdx.x * blockDim.x + threadIdx.x) >> 5;
    const int lane = threadIdx.x & 31;
    if (d >= N) return;

    const int beg = row_ptr[d];
    const int end = row_ptr[d + 1];

    float2 acc = make_float2(0.f, 0.f);
    const __half* __restrict__ P = p_half;

    int j = beg;
    for (; j + 8 <= end; j += 8) {
        int2 e[8];
#pragma unroll
        for (int q = 0; q < 8; q++) e[q] = __ldg(&edge_sorted[j + q]);
        __half2 pv[8];
#pragma unroll
        for (int q = 0; q < 8; q++)
            pv[q] = *(const __half2*)(P + (size_t)e[q].x * 64 + lane * 2);
#pragma unroll
        for (int q = 0; q < 8; q++) {
            const float w = __int_as_float(e[q].y);
            const float2 f = __half22float2(pv[q]);
            acc.x += w * f.x; acc.y += w * f.y;
        }
    }
    for (; j < end; j++) {
        const int2 e = __ldg(&edge_sorted[j]);
        const float w = __int_as_float(e.y);
        const float2 f = __half22float2(*(const __half2*)(P + (size_t)e.x * 64 + lane * 2));
        acc.x += w * f.x; acc.y += w * f.y;
    }

    const float2 bv = *(const float2*)(b2 + lane * 2);
    float2 o; o.x = acc.x + bv.x; o.y = acc.y + bv.y;
    *(float2*)(out + (size_t)d * 64 + lane * 2) = o;
}

// ---------------------------------------------------------------------------
// kernel_launch
// inputs: x, edge_weight, W1, b1, W2, b2, src, dst, n_nodes
// Fork: main = prep+gemm1 (wmma fp16), s2 = CSR build. Join before spmm1.
// ---------------------------------------------------------------------------
extern "C" void kernel_launch(void* const* d_in, const int* in_sizes, int n_in,
                              void* d_out, int out_size)
{
    const float* x   = (const float*)d_in[0];
    const float* ew  = (const float*)d_in[1];
    const float* W1  = (const float*)d_in[2];
    const float* b1  = (const float*)d_in[3];
    const float* W2  = (const float*)d_in[4];
    const float* b2  = (const float*)d_in[5];
    const int*   src = (const int*)d_in[6];
    const int*   dst = (const int*)d_in[7];

    const int N = in_sizes[0] / 128;
    const int E = in_sizes[1];
    float* out = (float*)d_out;

    const int nchunks = (N + SCAN_CHUNK - 1) / SCAN_CHUNK;

    static cudaStream_t s2 = nullptr;
    static cudaEvent_t  ev_fork = nullptr, ev_join = nullptr;
    static bool tried = false;
    if (!tried) {
        tried = true;
        cudaFuncSetAttribute(gemm1_wmma, cudaFuncAttributeMaxDynamicSharedMemorySize,
                             G1_SMEM_BYTES);
        if (cudaStreamCreateWithFlags(&s2, cudaStreamNonBlocking) != cudaSuccess) s2 = nullptr;
        if (s2) {
            cudaEventCreateWithFlags(&ev_fork, cudaEventDisableTiming);
            cudaEventCreateWithFlags(&ev_join, cudaEventDisableTiming);
        }
    }

    cudaStream_t cs = s2 ? s2 : (cudaStream_t)0;

    if (s2) {
        cudaEventRecord(ev_fork, 0);
        cudaStreamWaitEvent(s2, ev_fork, 0);
    }

    // --- CSR build on secondary stream (independent of gemm1) ---
    k_zero_deg   <<<(N + 255) / 256, 256, 0, cs>>>(N);
    k_hist       <<<(E + 255) / 256, 256, 0, cs>>>(dst, E);
    k_part_sums  <<<nchunks, 256, 0, cs>>>(N);
    k_scan_parts <<<1, 128, 0, cs>>>(nchunks, N, E);
    k_scan_chunks<<<nchunks, SCAN_CHUNK, 0, cs>>>(N);
    k_scatter    <<<(E + 255) / 256, 256, 0, cs>>>(src, dst, ew, E);

    if (s2) cudaEventRecord(ev_join, s2);

    // --- main stream: W1 fp16 prep + tensor-core gemm1, overlapped with CSR ---
    k_prep_w1<<<(128 * 128 + 255) / 256, 256>>>(W1);
    gemm1_wmma<<<(N + 127) / 128, 256, G1_SMEM_BYTES>>>(x, N);

    if (s2) cudaStreamWaitEvent((cudaStream_t)0, ev_join, 0);

    // h = relu(spmm(A, g) + b1) * mask * 2    (fp16 in/out, threefry in epilogue)
    spmm1_fused<<<(N * 32 + 255) / 256, 256>>>(b1, N);
    // p = h @ W2                               (fp16 in/out, fp32 math)
    gemm2_k128<<<(N + 127) / 128, 256>>>(W2, N);
    // out = spmm(A, p) + b2
    spmm2_fused<<<(N * 32 + 255) / 256, 256>>>(b2, out, N);
}

// round 15
// speedup vs baseline: 1.4845x; 1.1516x over previous
#include <cuda_runtime.h>
#include <cuda_fp16.h>
#include <mma.h>
#include <cstdint>
#include <cstddef>

using namespace nvcuda;

// ---------------------------------------------------------------------------
// Fixed shapes: N=100000, E=1600000, F 128 -> 128 -> 64
// ---------------------------------------------------------------------------
#define MAX_N 100000
#define MAX_E 1600000
#define SCAN_CHUNK 1024
#define MAX_CHUNKS ((MAX_N + SCAN_CHUNK - 1) / SCAN_CHUNK)   // 98

// Scratch (device BSS — no allocation inside kernel_launch)
__device__ __half g_half[(size_t)MAX_N * 128];   // x @ W1, fp16
__device__ __half h_half[(size_t)MAX_N * 128];   // relu+bias+dropout, fp16
__device__ __half p_half[(size_t)MAX_N * 64];    // h @ W2, fp16
__device__ __align__(16) __half w1_fp16[128 * 128];  // W1 pre-converted
__device__ __align__(16) __half w2_fp16[128 * 64];   // W2 pre-converted

__device__ int   deg_buf   [MAX_N];
__device__ int   row_ptr   [MAX_N + 1];
__device__ int   cursor    [MAX_N];
__device__ int   part_buf  [MAX_CHUNKS];
__device__ int2  edge_sorted[MAX_E];             // packed (src, w_bits)

// ---------------------------------------------------------------------------
// Threefry-2x32, key = (0, 42) — bit-exact replica of jax threefry2x32 core
// ---------------------------------------------------------------------------
__device__ __forceinline__ void threefry_0_42(uint32_t x0, uint32_t x1,
                                              uint32_t& o0, uint32_t& o1)
{
    const uint32_t k0 = 0u, k1 = 42u;
    const uint32_t k2 = k0 ^ k1 ^ 0x1BD11BDAu;
    x0 += k0; x1 += k1;
#define TF_R(r) { x0 += x1; x1 = (x1 << (r)) | (x1 >> (32 - (r))); x1 ^= x0; }
    TF_R(13) TF_R(15) TF_R(26) TF_R(6)   x0 += k1; x1 += k2 + 1u;
    TF_R(17) TF_R(29) TF_R(16) TF_R(24)  x0 += k2; x1 += k0 + 2u;
    TF_R(13) TF_R(15) TF_R(26) TF_R(6)   x0 += k0; x1 += k1 + 3u;
    TF_R(17) TF_R(29) TF_R(16) TF_R(24)  x0 += k1; x1 += k2 + 4u;
    TF_R(13) TF_R(15) TF_R(26) TF_R(6)   x0 += k2; x1 += k0 + 5u;
#undef TF_R
    o0 = x0; o1 = x1;
}

__device__ __forceinline__ bool drop_mask(uint32_t i)
{
    uint32_t o0, o1;
    threefry_0_42(0u, i, o0, o1);
    return ((o0 ^ o1) & 0x80000000u) != 0u;   // true = drop (XOR-fold)
}

// ===========================================================================
// Prep: W1, W2 fp32 -> fp16 global images (once per launch; tiny, fork phase)
// ===========================================================================
__global__ void k_prep_w(const float* __restrict__ W1, const float* __restrict__ W2)
{
    const int i = blockIdx.x * blockDim.x + threadIdx.x;
    if (i < 128 * 128) w1_fp16[i] = __float2half_rn(W1[i]);
    if (i < 128 * 64)  w2_fp16[i] = __float2half_rn(W2[i]);
}

// ===========================================================================
// GEMM1 (wmma fp16, single pass): g_half[M,128] = x[M,128] @ W1[128,128]
// CTA = 128 rows, 256 threads = 8 warps (2x4). Warp tile 64x32 (4x2 frags).
// ===========================================================================
#define G1_LD  136                                     // anti-conflict pad
#define G1_B_OFF   (128 * G1_LD)                       // halfs
#define G1_SMEM_HALFS (2 * 128 * G1_LD)
#define G1_STAGE_OFF  (G1_SMEM_HALFS * 2)              // bytes
#define G1_SMEM_BYTES (G1_SMEM_HALFS * 2 + 8 * 16 * 16 * 4)

__global__ void __launch_bounds__(256, 2)
gemm1_wmma(const float* __restrict__ x, int M)
{
    extern __shared__ __align__(16) char smem_raw[];
    __half* Ah = (__half*)smem_raw;                    // [128][G1_LD]
    __half* Bh = Ah + G1_B_OFF;                        // [128][G1_LD]
    float*  stage = (float*)(smem_raw + G1_STAGE_OFF); // [8][256]

    const int tid = threadIdx.x;
    const int wid = tid >> 5;
    const int lane = tid & 31;
    const int m0  = blockIdx.x * 128;
    const int warp_m = wid >> 2;   // 0..1
    const int warp_n = wid & 3;    // 0..3

    for (int i = tid; i < 128 * 32; i += 256) {        // float4 indices
        const int row = i >> 5;
        const int c4  = (i & 31) * 4;
        int grow = m0 + row;
        if (grow > M - 1) grow = M - 1;
        const float4 v = __ldg((const float4*)(x + (size_t)grow * 128 + c4));
        const __half2 h0 = __floats2half2_rn(v.x, v.y);
        const __half2 h1 = __floats2half2_rn(v.z, v.w);
        *(__half2*)(Ah + row * G1_LD + c4)     = h0;
        *(__half2*)(Ah + row * G1_LD + c4 + 2) = h1;
    }
    for (int i = tid; i < 128 * 16; i += 256) {        // uint4 indices
        const int row = i >> 4;
        const int c8  = (i & 15) * 8;
        *(uint4*)(Bh + row * G1_LD + c8) =
            *(const uint4*)(w1_fp16 + row * 128 + c8);
    }
    __syncthreads();

    wmma::fragment<wmma::accumulator, 16, 16, 16, float> acc[4][2];
#pragma unroll
    for (int mf = 0; mf < 4; mf++)
#pragma unroll
        for (int nf = 0; nf < 2; nf++)
            wmma::fill_fragment(acc[mf][nf], 0.0f);

#pragma unroll
    for (int ks = 0; ks < 8; ks++) {
        wmma::fragment<wmma::matrix_b, 16, 16, 16, __half, wmma::row_major> bf[2];
#pragma unroll
        for (int nf = 0; nf < 2; nf++)
            wmma::load_matrix_sync(bf[nf],
                Bh + ks * 16 * G1_LD + warp_n * 32 + nf * 16, G1_LD);
#pragma unroll
        for (int mf = 0; mf < 4; mf++) {
            wmma::fragment<wmma::matrix_a, 16, 16, 16, __half, wmma::row_major> af;
            wmma::load_matrix_sync(af,
                Ah + (warp_m * 64 + mf * 16) * G1_LD + ks * 16, G1_LD);
#pragma unroll
            for (int nf = 0; nf < 2; nf++)
                wmma::mma_sync(acc[mf][nf], af, bf[nf], acc[mf][nf]);
        }
    }

    float* st = stage + wid * 256;
#pragma unroll
    for (int mf = 0; mf < 4; mf++) {
        const int r0 = m0 + warp_m * 64 + mf * 16;
        const bool valid = (r0 + 16 <= M);             // M % 16 == 0
#pragma unroll
        for (int nf = 0; nf < 2; nf++) {
            wmma::store_matrix_sync(st, acc[mf][nf], 16, wmma::mem_row_major);
            __syncwarp();
            if (valid) {
                const int row = lane >> 1;
                const int c0  = (lane & 1) * 8;
                const float* s = st + row * 16 + c0;
                uint4 o;
                __half2 q0 = __floats2half2_rn(s[0], s[1]);
                __half2 q1 = __floats2half2_rn(s[2], s[3]);
                __half2 q2 = __floats2half2_rn(s[4], s[5]);
                __half2 q3 = __floats2half2_rn(s[6], s[7]);
                o.x = *reinterpret_cast<const uint32_t*>(&q0);
                o.y = *reinterpret_cast<const uint32_t*>(&q1);
                o.z = *reinterpret_cast<const uint32_t*>(&q2);
                o.w = *reinterpret_cast<const uint32_t*>(&q3);
                *(uint4*)(g_half + (size_t)(r0 + row) * 128
                          + warp_n * 32 + nf * 16 + c0) = o;
            }
            __syncwarp();
        }
    }
}

// ===========================================================================
// GEMM2 (wmma fp16): p_half[M,64] = h_half[M,128] @ W2[128,64]
// CTA = 128 rows, 256 threads = 8 warps (4x2). Warp tile 32x32 (2x2 frags).
// A is already fp16 in global (h_half) — pure copy into SMEM, no conversion.
// ===========================================================================
#define G2_LDA 136
#define G2_LDB 72
#define G2_A_HALFS (128 * G2_LDA)                      // 17408
#define G2_B_HALFS (128 * G2_LDB)                      // 9216
#define G2_STAGE_OFF ((G2_A_HALFS + G2_B_HALFS) * 2)   // bytes
#define G2_SMEM_BYTES (G2_STAGE_OFF + 8 * 16 * 16 * 4) // 53248 + 8192

__global__ void __launch_bounds__(256, 2)
gemm2_wmma(int M)
{
    extern __shared__ __align__(16) char smem_raw[];
    __half* Ah = (__half*)smem_raw;                    // [128][G2_LDA]
    __half* Bh = Ah + G2_A_HALFS;                      // [128][G2_LDB]
    float*  stage = (float*)(smem_raw + G2_STAGE_OFF); // [8][256]

    const int tid = threadIdx.x;
    const int wid = tid >> 5;
    const int lane = tid & 31;
    const int m0  = blockIdx.x * 128;
    const int warp_m = wid >> 1;   // 0..3
    const int warp_n = wid & 1;    // 0..1

    // Copy A tile (h_half, fp16) — 128 rows x 16 uint4
    for (int i = tid; i < 128 * 16; i += 256) {
        const int row = i >> 4;
        const int c8  = (i & 15) * 8;
        int grow = m0 + row;
        if (grow > M - 1) grow = M - 1;
        *(uint4*)(Ah + row * G2_LDA + c8) =
            *(const uint4*)(h_half + (size_t)grow * 128 + c8);
    }
    // Copy B (w2_fp16) — 128 rows x 8 uint4
    for (int i = tid; i < 128 * 8; i += 256) {
        const int row = i >> 3;
        const int c8  = (i & 7) * 8;
        *(uint4*)(Bh + row * G2_LDB + c8) =
            *(const uint4*)(w2_fp16 + row * 64 + c8);
    }
    __syncthreads();

    wmma::fragment<wmma::accumulator, 16, 16, 16, float> acc[2][2];
#pragma unroll
    for (int mf = 0; mf < 2; mf++)
#pragma unroll
        for (int nf = 0; nf < 2; nf++)
            wmma::fill_fragment(acc[mf][nf], 0.0f);

#pragma unroll
    for (int ks = 0; ks < 8; ks++) {
        wmma::fragment<wmma::matrix_b, 16, 16, 16, __half, wmma::row_major> bf[2];
#pragma unroll
        for (int nf = 0; nf < 2; nf++)
            wmma::load_matrix_sync(bf[nf],
                Bh + ks * 16 * G2_LDB + warp_n * 32 + nf * 16, G2_LDB);
#pragma unroll
        for (int mf = 0; mf < 2; mf++) {
            wmma::fragment<wmma::matrix_a, 16, 16, 16, __half, wmma::row_major> af;
            wmma::load_matrix_sync(af,
                Ah + (warp_m * 32 + mf * 16) * G2_LDA + ks * 16, G2_LDA);
#pragma unroll
            for (int nf = 0; nf < 2; nf++)
                wmma::mma_sync(acc[mf][nf], af, bf[nf], acc[mf][nf]);
        }
    }

    float* st = stage + wid * 256;
#pragma unroll
    for (int mf = 0; mf < 2; mf++) {
        const int r0 = m0 + warp_m * 32 + mf * 16;
        const bool valid = (r0 + 16 <= M);             // M % 16 == 0
#pragma unroll
        for (int nf = 0; nf < 2; nf++) {
            wmma::store_matrix_sync(st, acc[mf][nf], 16, wmma::mem_row_major);
            __syncwarp();
            if (valid) {
                const int row = lane >> 1;
                const int c0  = (lane & 1) * 8;
                const float* s = st + row * 16 + c0;
                uint4 o;
                __half2 q0 = __floats2half2_rn(s[0], s[1]);
                __half2 q1 = __floats2half2_rn(s[2], s[3]);
                __half2 q2 = __floats2half2_rn(s[4], s[5]);
                __half2 q3 = __floats2half2_rn(s[6], s[7]);
                o.x = *reinterpret_cast<const uint32_t*>(&q0);
                o.y = *reinterpret_cast<const uint32_t*>(&q1);
                o.z = *reinterpret_cast<const uint32_t*>(&q2);
                o.w = *reinterpret_cast<const uint32_t*>(&q3);
                *(uint4*)(p_half + (size_t)(r0 + row) * 64
                          + warp_n * 32 + nf * 16 + c0) = o;
            }
            __syncwarp();
        }
    }
}

// ===========================================================================
// CSR build: deg -> (part sums) -> scan(+inline offset) -> scatter
// ===========================================================================
__global__ void k_zero_deg(int N)
{
    const int i = blockIdx.x * blockDim.x + threadIdx.x;
    if (i < N) deg_buf[i] = 0;
}

__global__ void k_hist(const int* __restrict__ dst, int E)
{
    const int e = blockIdx.x * blockDim.x + threadIdx.x;
    if (e < E) atomicAdd(&deg_buf[dst[e]], 1);
}

__global__ void k_part_sums(int N)
{
    __shared__ int sm[256];
    const int b = blockIdx.x, t = threadIdx.x;
    int s = 0;
#pragma unroll
    for (int k = 0; k < 4; k++) {
        const int i = b * SCAN_CHUNK + k * 256 + t;
        if (i < N) s += deg_buf[i];
    }
    sm[t] = s; __syncthreads();
    for (int off = 128; off > 0; off >>= 1) {
        if (t < off) sm[t] += sm[t + off];
        __syncthreads();
    }
    if (t == 0) part_buf[b] = sm[0];
}

// Chunk scan with INLINE global-offset reduction (k_scan_parts eliminated).
// Each block reduces part_buf[0..b-1] (<=98 ints) itself.
__global__ void k_scan_chunks(int N, int E)
{
    __shared__ int sm[SCAN_CHUNK];
    __shared__ int smoff[128];
    const int b = blockIdx.x, t = threadIdx.x;
    const int i = b * SCAN_CHUNK + t;
    const int v = (i < N) ? deg_buf[i] : 0;
    sm[t] = v;
    if (t < 128) smoff[t] = (t < b) ? part_buf[t] : 0;   // MAX_CHUNKS <= 128
    __syncthreads();
    // reduce smoff -> smoff[0] = exclusive offset for this chunk
    for (int off = 64; off > 0; off >>= 1) {
        if (t < off) smoff[t] += smoff[t + off];
        __syncthreads();
    }
    // Hillis-Steele inclusive scan of this chunk
#pragma unroll
    for (int off = 1; off < SCAN_CHUNK; off <<= 1) {
        const int x = (t >= off) ? sm[t - off] : 0;
        __syncthreads();
        sm[t] += x;
        __syncthreads();
    }
    const int offset = smoff[0];
    if (i < N) {
        const int ex = sm[t] - v + offset;
        row_ptr[i] = ex;
        cursor[i]  = ex;
    }
    if (b == 0 && t == 0) row_ptr[N] = E;
}

__global__ void k_scatter(const int* __restrict__ src, const int* __restrict__ dst,
                          const float* __restrict__ ew, int E)
{
    const int e = blockIdx.x * blockDim.x + threadIdx.x;
    if (e >= E) return;
    const int pos = atomicAdd(&cursor[dst[e]], 1);
    int2 pkt;
    pkt.x = src[e];
    pkt.y = __float_as_int(ew[e]);
    edge_sorted[pos] = pkt;
}

// ===========================================================================
// SpMM1 (CSR, F=128, fp16 gather) + bias/relu/dropout epilogue (fp16 out).
// ===========================================================================
__global__ void __launch_bounds__(256)
spmm1_fused(const float* __restrict__ b1, int N)
{
    const int d    = (blockIdx.x * blockDim.x + threadIdx.x) >> 5;
    const int lane = threadIdx.x & 31;
    if (d >= N) return;

    const int beg = row_ptr[d];
    const int end = row_ptr[d + 1];

    float4 acc = make_float4(0.f, 0.f, 0.f, 0.f);
    const __half* __restrict__ G = g_half;

    int j = beg;
    for (; j + 8 <= end; j += 8) {
        int2 e[8];
#pragma unroll
        for (int q = 0; q < 8; q++) e[q] = __ldg(&edge_sorted[j + q]);
        uint2 gv[8];
#pragma unroll
        for (int q = 0; q < 8; q++)
            gv[q] = *(const uint2*)(G + (size_t)e[q].x * 128 + lane * 4);
#pragma unroll
        for (int q = 0; q < 8; q++) {
            const float w = __int_as_float(e[q].y);
            const float2 f0 = __half22float2(*reinterpret_cast<const __half2*>(&gv[q].x));
            const float2 f1 = __half22float2(*reinterpret_cast<const __half2*>(&gv[q].y));
            acc.x += w * f0.x; acc.y += w * f0.y;
            acc.z += w * f1.x; acc.w += w * f1.y;
        }
    }
    for (; j < end; j++) {
        const int2 e = __ldg(&edge_sorted[j]);
        const float w = __int_as_float(e.y);
        const uint2 gv = *(const uint2*)(G + (size_t)e.x * 128 + lane * 4);
        const float2 f0 = __half22float2(*reinterpret_cast<const __half2*>(&gv.x));
        const float2 f1 = __half22float2(*reinterpret_cast<const __half2*>(&gv.y));
        acc.x += w * f0.x; acc.y += w * f0.y;
        acc.z += w * f1.x; acc.w += w * f1.y;
    }

    const float4 bv = *(const float4*)(b1 + lane * 4);
    const uint32_t base = (uint32_t)d * 128u + (uint32_t)lane * 4u;

    float v0 = fmaxf(acc.x + bv.x, 0.f);
    float v1 = fmaxf(acc.y + bv.y, 0.f);
    float v2 = fmaxf(acc.z + bv.z, 0.f);
    float v3 = fmaxf(acc.w + bv.w, 0.f);
    v0 = drop_mask(base + 0u) ? 0.f : v0 * 2.f;
    v1 = drop_mask(base + 1u) ? 0.f : v1 * 2.f;
    v2 = drop_mask(base + 2u) ? 0.f : v2 * 2.f;
    v3 = drop_mask(base + 3u) ? 0.f : v3 * 2.f;

    uint2 o;
    const __half2 h0 = __floats2half2_rn(v0, v1);
    const __half2 h1 = __floats2half2_rn(v2, v3);
    o.x = *reinterpret_cast<const uint32_t*>(&h0);
    o.y = *reinterpret_cast<const uint32_t*>(&h1);
    *(uint2*)(h_half + (size_t)d * 128 + lane * 4) = o;
}

// ===========================================================================
// SpMM2 (CSR, F=64, fp16 gather) fused with +b2. Lane owns 2 features.
// ===========================================================================
__global__ void __launch_bounds__(256)
spmm2_fused(const float* __restrict__ b2, float* __restrict__ out, int N)
{
    const int d    = (blockIdx.x * blockDim.x + threadIdx.x) >> 5;
    const int lane = threadIdx.x & 31;
    if (d >= N) return;

    const int beg = row_ptr[d];
    const int end = row_ptr[d + 1];

    float2 acc = make_float2(0.f, 0.f);
    const __half* __restrict__ P = p_half;

    int j = beg;
    for (; j + 8 <= end; j += 8) {
        int2 e[8];
#pragma unroll
        for (int q = 0; q < 8; q++) e[q] = __ldg(&edge_sorted[j + q]);
        __half2 pv[8];
#pragma unroll
        for (int q = 0; q < 8; q++)
            pv[q] = *(const __half2*)(P + (size_t)e[q].x * 64 + lane * 2);
#pragma unroll
        for (int q = 0; q < 8; q++) {
            const float w = __int_as_float(e[q].y);
            const float2 f = __half22float2(pv[q]);
            acc.x += w * f.x; acc.y += w * f.y;
        }
    }
    for (; j < end; j++) {
        const int2 e = __ldg(&edge_sorted[j]);
        const float w = __int_as_float(e.y);
        const float2 f = __half22float2(*(const __half2*)(P + (size_t)e.x * 64 + lane * 2));
        acc.x += w * f.x; acc.y += w * f.y;
    }

    const float2 bv = *(const float2*)(b2 + lane * 2);
    float2 o; o.x = acc.x + bv.x; o.y = acc.y + bv.y;
    *(float2*)(out + (size_t)d * 64 + lane * 2) = o;
}

// ---------------------------------------------------------------------------
// kernel_launch
// inputs: x, edge_weight, W1, b1, W2, b2, src, dst, n_nodes
// Fork: main = prep + gemm1 (wmma), s2 = CSR build (5 kernels). Join.
// ---------------------------------------------------------------------------
extern "C" void kernel_launch(void* const* d_in, const int* in_sizes, int n_in,
                              void* d_out, int out_size)
{
    const float* x   = (const float*)d_in[0];
    const float* ew  = (const float*)d_in[1];
    const float* W1  = (const float*)d_in[2];
    const float* b1  = (const float*)d_in[3];
    const float* W2  = (const float*)d_in[4];
    const float* b2  = (const float*)d_in[5];
    const int*   src = (const int*)d_in[6];
    const int*   dst = (const int*)d_in[7];

    const int N = in_sizes[0] / 128;
    const int E = in_sizes[1];
    float* out = (float*)d_out;

    const int nchunks = (N + SCAN_CHUNK - 1) / SCAN_CHUNK;

    static cudaStream_t s2 = nullptr;
    static cudaEvent_t  ev_fork = nullptr, ev_join = nullptr;
    static bool tried = false;
    if (!tried) {
        tried = true;
        cudaFuncSetAttribute(gemm1_wmma, cudaFuncAttributeMaxDynamicSharedMemorySize,
                             G1_SMEM_BYTES);
        cudaFuncSetAttribute(gemm2_wmma, cudaFuncAttributeMaxDynamicSharedMemorySize,
                             G2_SMEM_BYTES);
        if (cudaStreamCreateWithFlags(&s2, cudaStreamNonBlocking) != cudaSuccess) s2 = nullptr;
        if (s2) {
            cudaEventCreateWithFlags(&ev_fork, cudaEventDisableTiming);
            cudaEventCreateWithFlags(&ev_join, cudaEventDisableTiming);
        }
    }

    cudaStream_t cs = s2 ? s2 : (cudaStream_t)0;

    if (s2) {
        cudaEventRecord(ev_fork, 0);
        cudaStreamWaitEvent(s2, ev_fork, 0);
    }

    // --- CSR build on secondary stream (independent of gemm1) ---
    k_zero_deg   <<<(N + 255) / 256, 256, 0, cs>>>(N);
    k_hist       <<<(E + 255) / 256, 256, 0, cs>>>(dst, E);
    k_part_sums  <<<nchunks, 256, 0, cs>>>(N);
    k_scan_chunks<<<nchunks, SCAN_CHUNK, 0, cs>>>(N, E);
    k_scatter    <<<(E + 255) / 256, 256, 0, cs>>>(src, dst, ew, E);

    if (s2) cudaEventRecord(ev_join, s2);

    // --- main stream: W1+W2 fp16 prep + tensor-core gemm1 ---
    k_prep_w<<<(128 * 128 + 255) / 256, 256>>>(W1, W2);
    gemm1_wmma<<<(N + 127) / 128, 256, G1_SMEM_BYTES>>>(x, N);

    if (s2) cudaStreamWaitEvent((cudaStream_t)0, ev_join, 0);

    // h = relu(spmm(A, g) + b1) * mask * 2
    spmm1_fused<<<(N * 32 + 255) / 256, 256>>>(b1, N);
    // p = h @ W2   (wmma fp16 — h already fp16, zero-conversion A path)
    gemm2_wmma<<<(N + 127) / 128, 256, G2_SMEM_BYTES>>>(N);
    // out = spmm(A, p) + b2
    spmm2_fused<<<(N * 32 + 255) / 256, 256>>>(b2, out, N);
}